// round 2
// baseline (speedup 1.0000x reference)
#include <cuda_runtime.h>
#include <math.h>

// ---------------- problem constants ----------------
#define BSZ     2048
#define NE      64
#define NA      16
#define DIN     128
#define HD      512          // H
#define AD      256          // A
#define NHD     8            // heads
#define ED      32           // A/NH
#define RLD     64           // H/8
#define OUTD    128
#define M_FULL  (BSZ*NE)     // 131072
#define M_AG    (BSZ*NA)     // 32768
#define GID     1536         // 3*H

// ---------------- scratch (device globals; no allocs allowed) ----------------
__device__ float g_embed[(size_t)M_FULL*HD];     // 268 MB
__device__ float g_K    [(size_t)M_FULL*AD];     // 134 MB
__device__ float g_V    [(size_t)M_FULL*AD];     // 134 MB
__device__ float g_Q    [(size_t)M_AG*AD];       //  33 MB
__device__ float g_att  [(size_t)M_AG*AD];       //  33 MB
__device__ float g_rew  [(size_t)BSZ*RLD];       // 0.5 MB
__device__ float g_gi   [(size_t)M_AG*GID];      // 201 MB
__device__ float g_gh   [(size_t)M_AG*GID];      // 201 MB
__device__ unsigned char g_obs_u8[(size_t)BSZ*NE*NE];  // 8.4 MB canonical masks
__device__ unsigned char g_sm_u8 [(size_t)BSZ*NE];     // 128 KB
__device__ int g_mask_mode;                            // 0=int32, 1=uint8, 2=float32

// ---------------- mask dtype detection (deterministic, 1 block) ----------------
__global__ void detect_mask_kernel(const unsigned int* __restrict__ w, int nwords)
{
    __shared__ int flags;
    if (threadIdx.x == 0) flags = 0;
    __syncthreads();
    int local = 0;
    for (int i = threadIdx.x; i < nwords; i += blockDim.x) {
        unsigned int v = w[i];
        if (v == 0x3F800000u) local |= 2;            // float 1.0f present
        else if (v > 1u) local |= 1;                 // packed-byte pattern
    }
    atomicOr(&flags, local);
    __syncthreads();
    if (threadIdx.x == 0) {
        int f = flags;
        g_mask_mode = (f & 2) ? 2 : ((f & 1) ? 1 : 0);
    }
}

__global__ void convert_mask_kernel(const void* __restrict__ src,
                                    unsigned char* __restrict__ dst, int n)
{
    int i = blockIdx.x * blockDim.x + threadIdx.x;
    if (i >= n) return;
    int mode = g_mask_mode;
    unsigned char v;
    if (mode == 1)      v = (((const unsigned char*)src)[i] != 0);
    else if (mode == 2) v = (((const unsigned int*)src)[i] != 0);   // float bits nonzero
    else                v = (((const int*)src)[i] != 0);
    dst[i] = v;
}

// ---------------- generic fp32 SGEMM: C = act(A@B + bias) ----------------
// 128x128 tile, BK=8, 256 threads, 8x8 per-thread microtile.
enum { MODE_DIR = 0, MODE_G16 = 1, MODE_CAT = 2 };

template<int MODE, bool RELU, bool MASK>
__global__ void __launch_bounds__(256, 2)
sgemm_kernel(const float* __restrict__ A, const float* __restrict__ B,
             const float* __restrict__ bias, float* __restrict__ C,
             int M, int N, int K,
             const float* __restrict__ A2, const float* __restrict__ A3,
             const unsigned char* __restrict__ smask)
{
    __shared__ float As[8][128];
    __shared__ float Bs[8][128];

    const int tid = threadIdx.x;
    const int bm = blockIdx.y * 128;
    const int bn = blockIdx.x * 128;

    const int ar = tid >> 1;             // 0..127
    const int ak = (tid & 1) * 4;        // 0 or 4
    const int br = tid >> 5;             // 0..7
    const int bc = (tid & 31) * 4;       // 0..124

    const int ty = tid >> 4, tx = tid & 15;
    const int row = ty * 8, col = tx * 8;

    const int m = bm + ar;
    const float* Arow = A;
    if (MODE == MODE_G16) Arow = A + (size_t)((m >> 4) * 64 + (m & 15)) * K;
    else if (MODE == MODE_DIR) Arow = A + (size_t)m * K;

    float acc[8][8];
    #pragma unroll
    for (int i = 0; i < 8; i++)
        #pragma unroll
        for (int j = 0; j < 8; j++) acc[i][j] = 0.0f;

    for (int k0 = 0; k0 < K; k0 += 8) {
        float4 av;
        if (MODE == MODE_CAT) {
            const int k = k0 + ak;
            if (k < 512) {
                av = *(const float4*)(A + (size_t)((m >> 4) * 64 + (m & 15)) * 512 + k);
            } else if (k < 768) {
                av = *(const float4*)(A2 + (size_t)m * 256 + (k - 512));
            } else {
                av = *(const float4*)(A3 + (size_t)(m >> 4) * 64 + (k - 768));
            }
        } else {
            av = *(const float4*)(Arow + k0 + ak);
        }
        As[ak + 0][ar] = av.x;
        As[ak + 1][ar] = av.y;
        As[ak + 2][ar] = av.z;
        As[ak + 3][ar] = av.w;

        *(float4*)&Bs[br][bc] = *(const float4*)(B + (size_t)(k0 + br) * N + bn + bc);
        __syncthreads();

        #pragma unroll
        for (int kk = 0; kk < 8; kk++) {
            float4 a0 = *(float4*)&As[kk][row];
            float4 a1 = *(float4*)&As[kk][row + 4];
            float4 b0 = *(float4*)&Bs[kk][col];
            float4 b1 = *(float4*)&Bs[kk][col + 4];
            float af[8] = {a0.x, a0.y, a0.z, a0.w, a1.x, a1.y, a1.z, a1.w};
            float bf[8] = {b0.x, b0.y, b0.z, b0.w, b1.x, b1.y, b1.z, b1.w};
            #pragma unroll
            for (int i = 0; i < 8; i++)
                #pragma unroll
                for (int j = 0; j < 8; j++)
                    acc[i][j] = fmaf(af[i], bf[j], acc[i][j]);
        }
        __syncthreads();
    }

    float bb[8];
    #pragma unroll
    for (int j = 0; j < 8; j++) bb[j] = bias[bn + col + j];

    #pragma unroll
    for (int i = 0; i < 8; i++) {
        const int gm = bm + row + i;
        float keep = 1.0f;
        if (MASK) {
            const int b = gm >> 4, q = gm & 15;
            if (smask[b * 64 + q]) keep = 0.0f;
        }
        float out[8];
        #pragma unroll
        for (int j = 0; j < 8; j++) {
            float v = acc[i][j] + bb[j];
            if (RELU) v = fmaxf(v, 0.0f);
            if (MASK) v *= keep;
            out[j] = v;
        }
        float* cp = C + (size_t)gm * N + bn + col;
        *(float4*)cp       = make_float4(out[0], out[1], out[2], out[3]);
        *(float4*)(cp + 4) = make_float4(out[4], out[5], out[6], out[7]);
    }
}

// ---------------- reward projection: relu(pre_rew @ W_rew + b_rew) ----------------
__global__ void rew_kernel(const float* __restrict__ prer,
                           const float* __restrict__ Wr,
                           const float* __restrict__ br,
                           float* __restrict__ out)
{
    int idx = blockIdx.x * blockDim.x + threadIdx.x;     // BSZ*RLD
    if (idx >= BSZ * RLD) return;
    int b = idx >> 6, j = idx & 63;
    out[idx] = fmaxf(fmaf(prer[b], Wr[j], br[j]), 0.0f);
}

// ---------------- attention: one block per (b, h) ----------------
__global__ void __launch_bounds__(128)
attn_kernel(const float* __restrict__ Qg, const float* __restrict__ Kg,
            const float* __restrict__ Vg, const unsigned char* __restrict__ obs,
            float* __restrict__ attOut)
{
    const int b = blockIdx.x >> 3;
    const int h = blockIdx.x & 7;
    const int tid = threadIdx.x;

    __shared__ float Qs[16][32];
    __shared__ float Ks[64][32];
    __shared__ float Vs[64][32];
    __shared__ float Ws[16][64];

    {
        int q = tid >> 3;
        int e4 = (tid & 7) * 4;
        *(float4*)&Qs[q][e4] =
            *(const float4*)(Qg + (size_t)(b * 16 + q) * 256 + h * 32 + e4);
    }
    #pragma unroll
    for (int i = 0; i < 4; i++) {
        int idx = tid + i * 128;     // 0..511
        int k = idx >> 3;
        int e4 = (idx & 7) * 4;
        *(float4*)&Ks[k][e4] =
            *(const float4*)(Kg + (size_t)(b * 64 + k) * 256 + h * 32 + e4);
        *(float4*)&Vs[k][e4] =
            *(const float4*)(Vg + (size_t)(b * 64 + k) * 256 + h * 32 + e4);
    }
    __syncthreads();

    const float scale = 0.17677669529663687f;  // 1/sqrt(32)
    #pragma unroll
    for (int i = 0; i < 8; i++) {
        int s = tid + i * 128;       // 0..1023
        int q = s >> 6;
        int k = s & 63;
        bool masked = (k == q) || (obs[(size_t)b * 4096 + q * 64 + k] != 0);
        float d;
        if (!masked) {
            d = 0.0f;
            #pragma unroll
            for (int e = 0; e < 32; e++) d = fmaf(Qs[q][e], Ks[k][e], d);
            d *= scale;
        } else {
            d = -INFINITY;
        }
        Ws[q][k] = d;
    }
    __syncthreads();

    {
        int q = tid >> 3;
        int l = tid & 7;
        float vals[8];
        float mx = -INFINITY;
        #pragma unroll
        for (int i = 0; i < 8; i++) { vals[i] = Ws[q][l + i * 8]; mx = fmaxf(mx, vals[i]); }
        #pragma unroll
        for (int d = 4; d > 0; d >>= 1) mx = fmaxf(mx, __shfl_xor_sync(0xffffffffu, mx, d, 8));
        if (mx == -INFINITY) {
            #pragma unroll
            for (int i = 0; i < 8; i++) vals[i] = 0.0f;
        } else {
            float sum = 0.0f;
            #pragma unroll
            for (int i = 0; i < 8; i++) { vals[i] = __expf(vals[i] - mx); sum += vals[i]; }
            #pragma unroll
            for (int d = 4; d > 0; d >>= 1) sum += __shfl_xor_sync(0xffffffffu, sum, d, 8);
            float inv = 1.0f / sum;
            #pragma unroll
            for (int i = 0; i < 8; i++) vals[i] *= inv;
        }
        #pragma unroll
        for (int i = 0; i < 8; i++) Ws[q][l + i * 8] = vals[i];
    }
    __syncthreads();

    #pragma unroll
    for (int i = 0; i < 4; i++) {
        int o = tid + i * 128;       // 0..511
        int q = o >> 5;
        int e = o & 31;
        float acc = 0.0f;
        #pragma unroll
        for (int k = 0; k < 64; k++) acc = fmaf(Ws[q][k], Vs[k][e], acc);
        attOut[(size_t)(b * 16 + q) * 256 + h * 32 + e] = acc;
    }
}

// ---------------- GRU pointwise: h = (1-z)*n + z*h_prev, masked ----------------
__device__ __forceinline__ float sigmoidf_(float x) { return 1.0f / (1.0f + __expf(-x)); }

__global__ void gru_kernel(const float* __restrict__ gi, const float* __restrict__ gh,
                           const float* __restrict__ preh,
                           const unsigned char* __restrict__ smask,
                           float* __restrict__ hOut)
{
    int t = blockIdx.x * blockDim.x + threadIdx.x;   // 0 .. M_AG*HD/4 - 1
    if (t >= M_AG * (HD / 4)) return;
    int m  = t >> 7;             // HD/4 = 128 float4 per row
    int j4 = (t & 127) * 4;
    size_t gb = (size_t)m * GID + j4;
    size_t hb = (size_t)m * HD + j4;

    float4 ir = *(const float4*)(gi + gb);
    float4 iz = *(const float4*)(gi + gb + 512);
    float4 in = *(const float4*)(gi + gb + 1024);
    float4 hr = *(const float4*)(gh + gb);
    float4 hz = *(const float4*)(gh + gb + 512);
    float4 hn = *(const float4*)(gh + gb + 1024);
    float4 hp = *(const float4*)(preh + hb);

    int b = m >> 4, q = m & 15;
    float keep = smask[b * 64 + q] ? 0.0f : 1.0f;

    float4 o;
    {
        float r = sigmoidf_(ir.x + hr.x), z = sigmoidf_(iz.x + hz.x);
        float n = tanhf(in.x + r * hn.x);
        o.x = keep * ((1.0f - z) * n + z * hp.x);
    }
    {
        float r = sigmoidf_(ir.y + hr.y), z = sigmoidf_(iz.y + hz.y);
        float n = tanhf(in.y + r * hn.y);
        o.y = keep * ((1.0f - z) * n + z * hp.y);
    }
    {
        float r = sigmoidf_(ir.z + hr.z), z = sigmoidf_(iz.z + hz.z);
        float n = tanhf(in.z + r * hn.z);
        o.z = keep * ((1.0f - z) * n + z * hp.z);
    }
    {
        float r = sigmoidf_(ir.w + hr.w), z = sigmoidf_(iz.w + hz.w);
        float n = tanhf(in.w + r * hn.w);
        o.w = keep * ((1.0f - z) * n + z * hp.w);
    }
    *(float4*)(hOut + hb) = o;
}

// ---------------- launch ----------------
extern "C" void kernel_launch(void* const* d_in, const int* in_sizes, int n_in,
                              void* d_out, int out_size)
{
    (void)in_sizes; (void)out_size;

    const float* state          = (const float*)d_in[0];
    const float* prer           = (const float*)d_in[1];
    const void*  obs_raw        = d_in[2];
    const void*  smask_raw      = d_in[3];
    const float* preh           = (const float*)d_in[4];

    // task_index is a plain python int in setup_inputs; it may or may not be
    // serialized as an input. Branch on n_in to locate the weights robustly.
    const int base = (n_in >= 22) ? 6 : 5;
    const float* Wst  = (const float*)d_in[base + 0];   const float* bst  = (const float*)d_in[base + 1];
    const float* Wr   = (const float*)d_in[base + 2];   const float* br   = (const float*)d_in[base + 3];
    const float* Wq   = (const float*)d_in[base + 4];   const float* bq   = (const float*)d_in[base + 5];
    const float* Wk   = (const float*)d_in[base + 6];   const float* bk   = (const float*)d_in[base + 7];
    const float* Wv   = (const float*)d_in[base + 8];   const float* bv   = (const float*)d_in[base + 9];
    const float* Wih  = (const float*)d_in[base + 10];  const float* bih  = (const float*)d_in[base + 11];
    const float* Whh  = (const float*)d_in[base + 12];  const float* bhh  = (const float*)d_in[base + 13];
    const float* Wout = (const float*)d_in[base + 14];  const float* bout = (const float*)d_in[base + 15];

    float* params = (float*)d_out;                         // (BSZ, NA, OUTD)
    float* hOut   = params + (size_t)M_AG * OUTD;          // (BSZ, NA, HD)

    float *embed, *Kb, *Vb, *Qb, *attb, *rewb, *gib, *ghb;
    unsigned char *obs, *smask;
    cudaGetSymbolAddress((void**)&embed, g_embed);
    cudaGetSymbolAddress((void**)&Kb,    g_K);
    cudaGetSymbolAddress((void**)&Vb,    g_V);
    cudaGetSymbolAddress((void**)&Qb,    g_Q);
    cudaGetSymbolAddress((void**)&attb,  g_att);
    cudaGetSymbolAddress((void**)&rewb,  g_rew);
    cudaGetSymbolAddress((void**)&gib,   g_gi);
    cudaGetSymbolAddress((void**)&ghb,   g_gh);
    cudaGetSymbolAddress((void**)&obs,   g_obs_u8);
    cudaGetSymbolAddress((void**)&smask, g_sm_u8);

    dim3 blk(256);

    // 0. mask dtype detection + canonicalization to uint8
    //    (scan count = elemcount/4 words, safe for 1/4-byte encodings)
    detect_mask_kernel<<<1, 256>>>((const unsigned int*)obs_raw, (BSZ * NE * NE) / 4);
    convert_mask_kernel<<<(BSZ * NE * NE + 255) / 256, blk>>>(obs_raw, obs, BSZ * NE * NE);
    convert_mask_kernel<<<(BSZ * NE + 255) / 256, blk>>>(smask_raw, smask, BSZ * NE);

    // 1. embed = relu(state @ W_state + b) : (131072 x 512), K=128
    sgemm_kernel<MODE_DIR, true, false><<<dim3(HD/128, M_FULL/128), blk>>>(
        state, Wst, bst, embed, M_FULL, HD, DIN, nullptr, nullptr, nullptr);

    // 2. K = embed @ W_k + b : (131072 x 256), K=512
    sgemm_kernel<MODE_DIR, false, false><<<dim3(AD/128, M_FULL/128), blk>>>(
        embed, Wk, bk, Kb, M_FULL, AD, HD, nullptr, nullptr, nullptr);

    // 3. V = relu(embed @ W_v + b)
    sgemm_kernel<MODE_DIR, true, false><<<dim3(AD/128, M_FULL/128), blk>>>(
        embed, Wv, bv, Vb, M_FULL, AD, HD, nullptr, nullptr, nullptr);

    // 4. Q = embed[:, :16] @ W_q + b : gathered rows, (32768 x 256)
    sgemm_kernel<MODE_G16, false, false><<<dim3(AD/128, M_AG/128), blk>>>(
        embed, Wq, bq, Qb, M_AG, AD, HD, nullptr, nullptr, nullptr);

    // 5. rew = relu(pre_rew @ W_rew + b)
    rew_kernel<<<(BSZ * RLD + 255) / 256, blk>>>(prer, Wr, br, rewb);

    // 6. attention per (b, h)
    attn_kernel<<<BSZ * NHD, 128>>>(Qb, Kb, Vb, obs, attb);

    // 7. gi = concat(embed16, att, rew) @ W_ih + b : (32768 x 1536), K=832
    sgemm_kernel<MODE_CAT, false, false><<<dim3(GID/128, M_AG/128), blk>>>(
        embed, Wih, bih, gib, M_AG, GID, HD + AD + RLD, attb, rewb, nullptr);

    // 8. gh = pre_hidden @ W_hh + b : (32768 x 1536), K=512
    sgemm_kernel<MODE_DIR, false, false><<<dim3(GID/128, M_AG/128), blk>>>(
        preh, Whh, bhh, ghb, M_AG, GID, HD, nullptr, nullptr, nullptr);

    // 9. GRU pointwise -> h (masked), written directly into d_out
    gru_kernel<<<(M_AG * (HD/4) + 255) / 256, blk>>>(gib, ghb, preh, smask, hOut);

    // 10. params = h @ W_out + b, masked : (32768 x 128), K=512
    sgemm_kernel<MODE_DIR, false, true><<<dim3(OUTD/128, M_AG/128), blk>>>(
        hOut, Wout, bout, params, M_AG, OUTD, HD, nullptr, nullptr, smask);
}

// round 3
// speedup vs baseline: 1.8703x; 1.8703x over previous
#include <cuda_runtime.h>
#include <math.h>

// ---------------- problem constants ----------------
#define BSZ     2048
#define NE      64
#define NA      16
#define DIN     128
#define HD      512          // H
#define AD      256          // A
#define NHD     8            // heads
#define ED      32           // A/NH
#define RLD     64           // H/8
#define OUTD    128
#define M_FULL  (BSZ*NE)     // 131072
#define M_AG    (BSZ*NA)     // 32768
#define GID     1536         // 3*H

// ---------------- scratch (device globals; no allocs allowed) ----------------
__device__ float g_embed[(size_t)M_FULL*HD];
__device__ float g_K    [(size_t)M_FULL*AD];
__device__ float g_V    [(size_t)M_FULL*AD];
__device__ float g_Q    [(size_t)M_AG*AD];
__device__ float g_att  [(size_t)M_AG*AD];
__device__ float g_rew  [(size_t)BSZ*RLD];
__device__ float g_gi   [(size_t)M_AG*GID];
__device__ float g_gh   [(size_t)M_AG*GID];
__device__ unsigned char g_obs_u8[(size_t)BSZ*NE*NE];
__device__ unsigned char g_sm_u8 [(size_t)BSZ*NE];
__device__ int g_mask_flags;     // bit0: packed-byte pattern, bit1: float pattern

// ---------------- mask dtype detection (parallel, idempotent -> deterministic) --
__global__ void detect_reset_kernel() { g_mask_flags = 0; }

__global__ void detect_mask_kernel(const unsigned int* __restrict__ w, int nwords)
{
    int local = 0;
    for (int i = blockIdx.x * blockDim.x + threadIdx.x; i < nwords;
         i += gridDim.x * blockDim.x) {
        unsigned int v = w[i];
        if (v == 0x3F800000u) local |= 2;            // float 1.0f present
        else if (v > 1u) local |= 1;                 // packed-byte pattern
    }
    // warp-reduce then one atomic per warp
    for (int d = 16; d > 0; d >>= 1) local |= __shfl_xor_sync(0xffffffffu, local, d);
    if ((threadIdx.x & 31) == 0 && local) atomicOr(&g_mask_flags, local);
}

__global__ void convert_mask_kernel(const void* __restrict__ src,
                                    unsigned char* __restrict__ dst, int n)
{
    int i = blockIdx.x * blockDim.x + threadIdx.x;
    if (i >= n) return;
    int f = g_mask_flags;
    int mode = (f & 2) ? 2 : ((f & 1) ? 1 : 0);
    unsigned char v;
    if (mode == 1)      v = (((const unsigned char*)src)[i] != 0);
    else if (mode == 2) v = (((const unsigned int*)src)[i] != 0);
    else                v = (((const int*)src)[i] != 0);
    dst[i] = v;
}

// ---------------- fp32 SGEMM: C = act(A@B + bias) ----------------
// 128x128 tile, BK=8, 256 threads, 8x8 split microtile (rows ty*4/+64, cols tx*4/+64).
// 2-stage smem double buffer, register frag double buffer, conflict-free LDS.
enum { MODE_DIR = 0, MODE_G16 = 1, MODE_CAT = 2 };

template<int MODE>
__device__ __forceinline__ float4 loadA_tile(const float* __restrict__ A,
                                             const float* __restrict__ A2,
                                             const float* __restrict__ A3,
                                             const float* __restrict__ Arow,
                                             int m, int K, int k)
{
    if (MODE == MODE_CAT) {
        if (k < 512)
            return *(const float4*)(A + (size_t)((m >> 4) * 64 + (m & 15)) * 512 + k);
        else if (k < 768)
            return *(const float4*)(A2 + (size_t)m * 256 + (k - 512));
        else
            return *(const float4*)(A3 + (size_t)(m >> 4) * 64 + (k - 768));
    } else {
        return *(const float4*)(Arow + k);
    }
}

template<int MODE, bool RELU, bool MASK>
__global__ void __launch_bounds__(256, 2)
sgemm_kernel(const float* __restrict__ A, const float* __restrict__ B,
             const float* __restrict__ bias, float* __restrict__ C,
             int M, int N, int K,
             const float* __restrict__ A2, const float* __restrict__ A3,
             const unsigned char* __restrict__ smask)
{
    __shared__ float As[2][8][128];
    __shared__ float Bs[2][8][128];

    const int tid = threadIdx.x;
    const int bm = blockIdx.y * 128;
    const int bn = blockIdx.x * 128;

    // global->smem mapping (1 float4 per thread per tile for A and B)
    const int ar = tid >> 1;             // 0..127
    const int ak = (tid & 1) * 4;        // 0 or 4
    const int br = tid >> 5;             // 0..7
    const int bc = (tid & 31) * 4;       // 0..124

    // microtile mapping: conflict-free split
    const int ty4 = (tid >> 4) * 4;      // 0..60
    const int tx4 = (tid & 15) * 4;      // 0..60

    const int m = bm + ar;
    const float* Arow = A;
    if (MODE == MODE_G16) Arow = A + (size_t)((m >> 4) * 64 + (m & 15)) * K;
    else if (MODE == MODE_DIR) Arow = A + (size_t)m * K;

    float acc[8][8];
    #pragma unroll
    for (int i = 0; i < 8; i++)
        #pragma unroll
        for (int j = 0; j < 8; j++) acc[i][j] = 0.0f;

    float4 a0[2], a1[2], b0[2], b1[2];

    // prologue: stage 0
    {
        float4 av = loadA_tile<MODE>(A, A2, A3, Arow, m, K, ak);
        float4 bv = *(const float4*)(B + (size_t)br * N + bn + bc);
        As[0][ak + 0][ar] = av.x;
        As[0][ak + 1][ar] = av.y;
        As[0][ak + 2][ar] = av.z;
        As[0][ak + 3][ar] = av.w;
        *(float4*)&Bs[0][br][bc] = bv;
    }
    __syncthreads();
    a0[0] = *(float4*)&As[0][0][ty4];
    a1[0] = *(float4*)&As[0][0][64 + ty4];
    b0[0] = *(float4*)&Bs[0][0][tx4];
    b1[0] = *(float4*)&Bs[0][0][64 + tx4];

    int stage = 0;
    for (int k0 = 0; k0 < K; k0 += 8) {
        const bool hasNext = (k0 + 8) < K;
        float4 av, bv;
        if (hasNext) {
            av = loadA_tile<MODE>(A, A2, A3, Arow, m, K, k0 + 8 + ak);
            bv = *(const float4*)(B + (size_t)(k0 + 8 + br) * N + bn + bc);
        }

        #pragma unroll
        for (int kk = 0; kk < 8; kk++) {
            const int cur = kk & 1, nxt = cur ^ 1;
            if (kk < 7) {
                a0[nxt] = *(float4*)&As[stage][kk + 1][ty4];
                a1[nxt] = *(float4*)&As[stage][kk + 1][64 + ty4];
                b0[nxt] = *(float4*)&Bs[stage][kk + 1][tx4];
                b1[nxt] = *(float4*)&Bs[stage][kk + 1][64 + tx4];
            }
            const float af[8] = {a0[cur].x, a0[cur].y, a0[cur].z, a0[cur].w,
                                 a1[cur].x, a1[cur].y, a1[cur].z, a1[cur].w};
            const float bf[8] = {b0[cur].x, b0[cur].y, b0[cur].z, b0[cur].w,
                                 b1[cur].x, b1[cur].y, b1[cur].z, b1[cur].w};
            #pragma unroll
            for (int i = 0; i < 8; i++)
                #pragma unroll
                for (int j = 0; j < 8; j++)
                    acc[i][j] = fmaf(af[i], bf[j], acc[i][j]);
        }

        if (hasNext) {
            const int ns = stage ^ 1;
            As[ns][ak + 0][ar] = av.x;
            As[ns][ak + 1][ar] = av.y;
            As[ns][ak + 2][ar] = av.z;
            As[ns][ak + 3][ar] = av.w;
            *(float4*)&Bs[ns][br][bc] = bv;
            __syncthreads();
            stage = ns;
            a0[0] = *(float4*)&As[stage][0][ty4];
            a1[0] = *(float4*)&As[stage][0][64 + ty4];
            b0[0] = *(float4*)&Bs[stage][0][tx4];
            b1[0] = *(float4*)&Bs[stage][0][64 + tx4];
        }
    }

    // epilogue
    float bb0[4], bb1[4];
    #pragma unroll
    for (int j = 0; j < 4; j++) {
        bb0[j] = bias[bn + tx4 + j];
        bb1[j] = bias[bn + 64 + tx4 + j];
    }

    #pragma unroll
    for (int half = 0; half < 2; half++) {
        #pragma unroll
        for (int i = 0; i < 4; i++) {
            const int gm = bm + half * 64 + ty4 + i;
            float keep = 1.0f;
            if (MASK) {
                const int b = gm >> 4, q = gm & 15;
                if (smask[b * 64 + q]) keep = 0.0f;
            }
            const int ai = half * 4 + i;
            float o0[4], o1[4];
            #pragma unroll
            for (int j = 0; j < 4; j++) {
                float v0 = acc[ai][j] + bb0[j];
                float v1 = acc[ai][4 + j] + bb1[j];
                if (RELU) { v0 = fmaxf(v0, 0.0f); v1 = fmaxf(v1, 0.0f); }
                if (MASK) { v0 *= keep; v1 *= keep; }
                o0[j] = v0; o1[j] = v1;
            }
            float* cp = C + (size_t)gm * N + bn;
            *(float4*)(cp + tx4)      = make_float4(o0[0], o0[1], o0[2], o0[3]);
            *(float4*)(cp + 64 + tx4) = make_float4(o1[0], o1[1], o1[2], o1[3]);
        }
    }
}

// ---------------- reward projection ----------------
__global__ void rew_kernel(const float* __restrict__ prer,
                           const float* __restrict__ Wr,
                           const float* __restrict__ br,
                           float* __restrict__ out)
{
    int idx = blockIdx.x * blockDim.x + threadIdx.x;
    if (idx >= BSZ * RLD) return;
    int b = idx >> 6, j = idx & 63;
    out[idx] = fmaxf(fmaf(prer[b], Wr[j], br[j]), 0.0f);
}

// ---------------- attention: one block per (b, h) ----------------
__global__ void __launch_bounds__(128)
attn_kernel(const float* __restrict__ Qg, const float* __restrict__ Kg,
            const float* __restrict__ Vg, const unsigned char* __restrict__ obs,
            float* __restrict__ attOut)
{
    const int b = blockIdx.x >> 3;
    const int h = blockIdx.x & 7;
    const int tid = threadIdx.x;

    __shared__ float Qs[16][32];
    __shared__ float Ks[64][32];
    __shared__ float Vs[64][32];
    __shared__ float Ws[16][64];

    {
        int q = tid >> 3;
        int e4 = (tid & 7) * 4;
        *(float4*)&Qs[q][e4] =
            *(const float4*)(Qg + (size_t)(b * 16 + q) * 256 + h * 32 + e4);
    }
    #pragma unroll
    for (int i = 0; i < 4; i++) {
        int idx = tid + i * 128;
        int k = idx >> 3;
        int e4 = (idx & 7) * 4;
        *(float4*)&Ks[k][e4] =
            *(const float4*)(Kg + (size_t)(b * 64 + k) * 256 + h * 32 + e4);
        *(float4*)&Vs[k][e4] =
            *(const float4*)(Vg + (size_t)(b * 64 + k) * 256 + h * 32 + e4);
    }
    __syncthreads();

    const float scale = 0.17677669529663687f;  // 1/sqrt(32)
    #pragma unroll
    for (int i = 0; i < 8; i++) {
        int s = tid + i * 128;
        int q = s >> 6;
        int k = s & 63;
        bool masked = (k == q) || (obs[(size_t)b * 4096 + q * 64 + k] != 0);
        float d;
        if (!masked) {
            d = 0.0f;
            #pragma unroll
            for (int e = 0; e < 32; e++) d = fmaf(Qs[q][e], Ks[k][e], d);
            d *= scale;
        } else {
            d = -INFINITY;
        }
        Ws[q][k] = d;
    }
    __syncthreads();

    {
        int q = tid >> 3;
        int l = tid & 7;
        float vals[8];
        float mx = -INFINITY;
        #pragma unroll
        for (int i = 0; i < 8; i++) { vals[i] = Ws[q][l + i * 8]; mx = fmaxf(mx, vals[i]); }
        #pragma unroll
        for (int d = 4; d > 0; d >>= 1) mx = fmaxf(mx, __shfl_xor_sync(0xffffffffu, mx, d, 8));
        if (mx == -INFINITY) {
            #pragma unroll
            for (int i = 0; i < 8; i++) vals[i] = 0.0f;
        } else {
            float sum = 0.0f;
            #pragma unroll
            for (int i = 0; i < 8; i++) { vals[i] = __expf(vals[i] - mx); sum += vals[i]; }
            #pragma unroll
            for (int d = 4; d > 0; d >>= 1) sum += __shfl_xor_sync(0xffffffffu, sum, d, 8);
            float inv = 1.0f / sum;
            #pragma unroll
            for (int i = 0; i < 8; i++) vals[i] *= inv;
        }
        #pragma unroll
        for (int i = 0; i < 8; i++) Ws[q][l + i * 8] = vals[i];
    }
    __syncthreads();

    #pragma unroll
    for (int i = 0; i < 4; i++) {
        int o = tid + i * 128;
        int q = o >> 5;
        int e = o & 31;
        float acc = 0.0f;
        #pragma unroll
        for (int k = 0; k < 64; k++) acc = fmaf(Ws[q][k], Vs[k][e], acc);
        attOut[(size_t)(b * 16 + q) * 256 + h * 32 + e] = acc;
    }
}

// ---------------- GRU pointwise ----------------
__device__ __forceinline__ float sigmoidf_(float x) { return 1.0f / (1.0f + __expf(-x)); }

__global__ void gru_kernel(const float* __restrict__ gi, const float* __restrict__ gh,
                           const float* __restrict__ preh,
                           const unsigned char* __restrict__ smask,
                           float* __restrict__ hOut)
{
    int t = blockIdx.x * blockDim.x + threadIdx.x;
    if (t >= M_AG * (HD / 4)) return;
    int m  = t >> 7;
    int j4 = (t & 127) * 4;
    size_t gb = (size_t)m * GID + j4;
    size_t hb = (size_t)m * HD + j4;

    float4 ir = *(const float4*)(gi + gb);
    float4 iz = *(const float4*)(gi + gb + 512);
    float4 in = *(const float4*)(gi + gb + 1024);
    float4 hr = *(const float4*)(gh + gb);
    float4 hz = *(const float4*)(gh + gb + 512);
    float4 hn = *(const float4*)(gh + gb + 1024);
    float4 hp = *(const float4*)(preh + hb);

    int b = m >> 4, q = m & 15;
    float keep = smask[b * 64 + q] ? 0.0f : 1.0f;

    float4 o;
    {
        float r = sigmoidf_(ir.x + hr.x), z = sigmoidf_(iz.x + hz.x);
        float n = tanhf(in.x + r * hn.x);
        o.x = keep * ((1.0f - z) * n + z * hp.x);
    }
    {
        float r = sigmoidf_(ir.y + hr.y), z = sigmoidf_(iz.y + hz.y);
        float n = tanhf(in.y + r * hn.y);
        o.y = keep * ((1.0f - z) * n + z * hp.y);
    }
    {
        float r = sigmoidf_(ir.z + hr.z), z = sigmoidf_(iz.z + hz.z);
        float n = tanhf(in.z + r * hn.z);
        o.z = keep * ((1.0f - z) * n + z * hp.z);
    }
    {
        float r = sigmoidf_(ir.w + hr.w), z = sigmoidf_(iz.w + hz.w);
        float n = tanhf(in.w + r * hn.w);
        o.w = keep * ((1.0f - z) * n + z * hp.w);
    }
    *(float4*)(hOut + hb) = o;
}

// ---------------- launch ----------------
extern "C" void kernel_launch(void* const* d_in, const int* in_sizes, int n_in,
                              void* d_out, int out_size)
{
    (void)in_sizes; (void)out_size;

    const float* state          = (const float*)d_in[0];
    const float* prer           = (const float*)d_in[1];
    const void*  obs_raw        = d_in[2];
    const void*  smask_raw      = d_in[3];
    const float* preh           = (const float*)d_in[4];

    const int base = (n_in >= 22) ? 6 : 5;
    const float* Wst  = (const float*)d_in[base + 0];   const float* bst  = (const float*)d_in[base + 1];
    const float* Wr   = (const float*)d_in[base + 2];   const float* br   = (const float*)d_in[base + 3];
    const float* Wq   = (const float*)d_in[base + 4];   const float* bq   = (const float*)d_in[base + 5];
    const float* Wk   = (const float*)d_in[base + 6];   const float* bk   = (const float*)d_in[base + 7];
    const float* Wv   = (const float*)d_in[base + 8];   const float* bv   = (const float*)d_in[base + 9];
    const float* Wih  = (const float*)d_in[base + 10];  const float* bih  = (const float*)d_in[base + 11];
    const float* Whh  = (const float*)d_in[base + 12];  const float* bhh  = (const float*)d_in[base + 13];
    const float* Wout = (const float*)d_in[base + 14];  const float* bout = (const float*)d_in[base + 15];

    float* params = (float*)d_out;                         // (BSZ, NA, OUTD)
    float* hOut   = params + (size_t)M_AG * OUTD;          // (BSZ, NA, HD)

    float *embed, *Kb, *Vb, *Qb, *attb, *rewb, *gib, *ghb;
    unsigned char *obs, *smask;
    cudaGetSymbolAddress((void**)&embed, g_embed);
    cudaGetSymbolAddress((void**)&Kb,    g_K);
    cudaGetSymbolAddress((void**)&Vb,    g_V);
    cudaGetSymbolAddress((void**)&Qb,    g_Q);
    cudaGetSymbolAddress((void**)&attb,  g_att);
    cudaGetSymbolAddress((void**)&rewb,  g_rew);
    cudaGetSymbolAddress((void**)&gib,   g_gi);
    cudaGetSymbolAddress((void**)&ghb,   g_gh);
    cudaGetSymbolAddress((void**)&obs,   g_obs_u8);
    cudaGetSymbolAddress((void**)&smask, g_sm_u8);

    dim3 blk(256);

    // 0. mask dtype detection + canonicalization to uint8
    detect_reset_kernel<<<1, 1>>>();
    detect_mask_kernel<<<256, 256>>>((const unsigned int*)obs_raw, (BSZ * NE * NE) / 4);
    convert_mask_kernel<<<(BSZ * NE * NE + 255) / 256, blk>>>(obs_raw, obs, BSZ * NE * NE);
    convert_mask_kernel<<<(BSZ * NE + 255) / 256, blk>>>(smask_raw, smask, BSZ * NE);

    // 1. embed = relu(state @ W_state + b) : (131072 x 512), K=128
    sgemm_kernel<MODE_DIR, true, false><<<dim3(HD/128, M_FULL/128), blk>>>(
        state, Wst, bst, embed, M_FULL, HD, DIN, nullptr, nullptr, nullptr);

    // 2. K = embed @ W_k + b : (131072 x 256), K=512
    sgemm_kernel<MODE_DIR, false, false><<<dim3(AD/128, M_FULL/128), blk>>>(
        embed, Wk, bk, Kb, M_FULL, AD, HD, nullptr, nullptr, nullptr);

    // 3. V = relu(embed @ W_v + b)
    sgemm_kernel<MODE_DIR, true, false><<<dim3(AD/128, M_FULL/128), blk>>>(
        embed, Wv, bv, Vb, M_FULL, AD, HD, nullptr, nullptr, nullptr);

    // 4. Q = embed[:, :16] @ W_q + b : gathered rows, (32768 x 256)
    sgemm_kernel<MODE_G16, false, false><<<dim3(AD/128, M_AG/128), blk>>>(
        embed, Wq, bq, Qb, M_AG, AD, HD, nullptr, nullptr, nullptr);

    // 5. rew = relu(pre_rew @ W_rew + b)
    rew_kernel<<<(BSZ * RLD + 255) / 256, blk>>>(prer, Wr, br, rewb);

    // 6. attention per (b, h)
    attn_kernel<<<BSZ * NHD, 128>>>(Qb, Kb, Vb, obs, attb);

    // 7. gi = concat(embed16, att, rew) @ W_ih + b : (32768 x 1536), K=832
    sgemm_kernel<MODE_CAT, false, false><<<dim3(GID/128, M_AG/128), blk>>>(
        embed, Wih, bih, gib, M_AG, GID, HD + AD + RLD, attb, rewb, nullptr);

    // 8. gh = pre_hidden @ W_hh + b : (32768 x 1536), K=512
    sgemm_kernel<MODE_DIR, false, false><<<dim3(GID/128, M_AG/128), blk>>>(
        preh, Whh, bhh, ghb, M_AG, GID, HD, nullptr, nullptr, nullptr);

    // 9. GRU pointwise -> h (masked), written directly into d_out
    gru_kernel<<<(M_AG * (HD/4) + 255) / 256, blk>>>(gib, ghb, preh, smask, hOut);

    // 10. params = h @ W_out + b, masked : (32768 x 128), K=512
    sgemm_kernel<MODE_DIR, false, true><<<dim3(OUTD/128, M_AG/128), blk>>>(
        hOut, Wout, bout, params, M_AG, OUTD, HD, nullptr, nullptr, smask);
}

// round 5
// speedup vs baseline: 2.9050x; 1.5533x over previous
#include <cuda_runtime.h>
#include <cuda_bf16.h>
#include <math.h>
#include <stdint.h>

// ---------------- problem constants ----------------
#define BSZ     2048
#define NE      64
#define NA      16
#define DIN     128
#define HD      512
#define AD      256
#define NHD     8
#define ED      32
#define RLD     64
#define OUTD    128
#define M_FULL  (BSZ*NE)     // 131072
#define M_AG    (BSZ*NA)     // 32768
#define GID     1536         // 3*H

typedef __nv_bfloat16 bf16;

// ---------------- scratch (device globals; no allocs allowed) ----------------
__device__ __align__(256) float g_K  [(size_t)M_FULL*AD];
__device__ __align__(256) float g_V  [(size_t)M_FULL*AD];
__device__ __align__(256) float g_Q  [(size_t)M_AG*AD];
__device__ __align__(256) float g_gi [(size_t)M_AG*GID];
__device__ __align__(256) float g_gh [(size_t)M_AG*GID];
__device__ __align__(256) bf16 g_state_h[(size_t)M_FULL*DIN];
__device__ __align__(256) bf16 g_state_l[(size_t)M_FULL*DIN];
__device__ __align__(256) bf16 g_embed_h[(size_t)M_FULL*HD];
__device__ __align__(256) bf16 g_embed_l[(size_t)M_FULL*HD];
__device__ __align__(256) bf16 g_preh_h [(size_t)M_AG*HD];
__device__ __align__(256) bf16 g_preh_l [(size_t)M_AG*HD];
__device__ __align__(256) bf16 g_att_h  [(size_t)M_AG*AD];
__device__ __align__(256) bf16 g_att_l  [(size_t)M_AG*AD];
__device__ __align__(256) bf16 g_rew_h  [(size_t)BSZ*RLD];
__device__ __align__(256) bf16 g_rew_l  [(size_t)BSZ*RLD];
__device__ __align__(256) bf16 g_h_h    [(size_t)M_AG*HD];
__device__ __align__(256) bf16 g_h_l    [(size_t)M_AG*HD];
__device__ __align__(256) bf16 g_WstT_h[HD*DIN],  g_WstT_l[HD*DIN];
__device__ __align__(256) bf16 g_WqT_h [AD*HD],   g_WqT_l [AD*HD];
__device__ __align__(256) bf16 g_WkT_h [AD*HD],   g_WkT_l [AD*HD];
__device__ __align__(256) bf16 g_WvT_h [AD*HD],   g_WvT_l [AD*HD];
__device__ __align__(256) bf16 g_WihT_h[GID*832], g_WihT_l[GID*832];
__device__ __align__(256) bf16 g_WhhT_h[GID*HD],  g_WhhT_l[GID*HD];
__device__ __align__(256) bf16 g_WoutT_h[OUTD*HD],g_WoutT_l[OUTD*HD];
__device__ unsigned char g_obs_u8[(size_t)BSZ*NE*NE];
__device__ unsigned char g_sm_u8 [(size_t)BSZ*NE];
__device__ int g_mask_flags;

// ---------------- baseline-PTX helpers (no sm_103a-only features) ----------------
__device__ __forceinline__ uint32_t smem_u32(const void* p) {
    uint32_t a;
    asm("{ .reg .u64 t; cvta.to.shared.u64 t, %1; cvt.u32.u64 %0, t; }" : "=r"(a) : "l"(p));
    return a;
}
__device__ __forceinline__ void cp16(uint32_t dst, const void* src) {
    asm volatile("cp.async.cg.shared.global [%0], [%1], 16;" :: "r"(dst), "l"(src));
}
#define CP_COMMIT()  asm volatile("cp.async.commit_group;")
#define CP_WAIT(n)   asm volatile("cp.async.wait_group %0;" :: "n"(n))

__device__ __forceinline__ void ldm_x4(uint32_t* r, uint32_t addr) {
    asm volatile("ldmatrix.sync.aligned.m8n8.x4.shared.b16 {%0,%1,%2,%3}, [%4];"
                 : "=r"(r[0]), "=r"(r[1]), "=r"(r[2]), "=r"(r[3]) : "r"(addr));
}
__device__ __forceinline__ void mma16816(float* c, const uint32_t* a,
                                         uint32_t b0, uint32_t b1) {
    asm volatile(
        "mma.sync.aligned.m16n8k16.row.col.f32.bf16.bf16.f32 "
        "{%0,%1,%2,%3},{%4,%5,%6,%7},{%8,%9},{%0,%1,%2,%3};"
        : "+f"(c[0]), "+f"(c[1]), "+f"(c[2]), "+f"(c[3])
        : "r"(a[0]), "r"(a[1]), "r"(a[2]), "r"(a[3]), "r"(b0), "r"(b1));
}

// ---------------- mask dtype detection ----------------
__global__ void detect_reset_kernel() { g_mask_flags = 0; }
__global__ void detect_mask_kernel(const unsigned int* __restrict__ w, int nwords)
{
    int local = 0;
    for (int i = blockIdx.x * blockDim.x + threadIdx.x; i < nwords;
         i += gridDim.x * blockDim.x) {
        unsigned int v = w[i];
        if (v == 0x3F800000u) local |= 2;
        else if (v > 1u) local |= 1;
    }
    for (int d = 16; d > 0; d >>= 1) local |= __shfl_xor_sync(0xffffffffu, local, d);
    if ((threadIdx.x & 31) == 0 && local) atomicOr(&g_mask_flags, local);
}
__global__ void convert_mask_kernel(const void* __restrict__ src,
                                    unsigned char* __restrict__ dst, int n)
{
    int i = blockIdx.x * blockDim.x + threadIdx.x;
    if (i >= n) return;
    int f = g_mask_flags;
    int mode = (f & 2) ? 2 : ((f & 1) ? 1 : 0);
    unsigned char v;
    if (mode == 1)      v = (((const unsigned char*)src)[i] != 0);
    else if (mode == 2) v = (((const unsigned int*)src)[i] != 0);
    else                v = (((const int*)src)[i] != 0);
    dst[i] = v;
}

// ---------------- fp32 -> bf16 hi/lo conversions ----------------
__device__ __forceinline__ void split1(float v, bf16& h, bf16& l) {
    h = __float2bfloat16_rn(v);
    l = __float2bfloat16_rn(v - __bfloat162float(h));
}
__global__ void conv_split_kernel(const float* __restrict__ src,
                                  bf16* __restrict__ h, bf16* __restrict__ l, int n4)
{
    int i = blockIdx.x * blockDim.x + threadIdx.x;
    if (i >= n4) return;
    float4 v = ((const float4*)src)[i];
    bf16 h0,l0,h1,l1,h2,l2,h3,l3;
    split1(v.x,h0,l0); split1(v.y,h1,l1); split1(v.z,h2,l2); split1(v.w,h3,l3);
    uint32_t ph0 = (uint32_t)__bfloat16_as_ushort(h0) | ((uint32_t)__bfloat16_as_ushort(h1) << 16);
    uint32_t ph1 = (uint32_t)__bfloat16_as_ushort(h2) | ((uint32_t)__bfloat16_as_ushort(h3) << 16);
    uint32_t pl0 = (uint32_t)__bfloat16_as_ushort(l0) | ((uint32_t)__bfloat16_as_ushort(l1) << 16);
    uint32_t pl1 = (uint32_t)__bfloat16_as_ushort(l2) | ((uint32_t)__bfloat16_as_ushort(l3) << 16);
    ((uint2*)h)[i] = make_uint2(ph0, ph1);
    ((uint2*)l)[i] = make_uint2(pl0, pl1);
}
__global__ void conv_splitT_kernel(const float* __restrict__ src,
                                   bf16* __restrict__ h, bf16* __restrict__ l,
                                   int K, int N)
{
    int i = blockIdx.x * blockDim.x + threadIdx.x;
    if (i >= K * N) return;
    int k = i / N, n = i % N;
    bf16 hh, ll;
    split1(src[i], hh, ll);
    h[(size_t)n * K + k] = hh;
    l[(size_t)n * K + k] = ll;
}

// ---------------- HMMA bf16-split GEMM ----------------
// C[M,N] = act(A@B^T + bias), B given as [N,K].  128x128 tile, BK=32.
// smem stage: Ah | Al | Bh | Bl, each 128 rows x (32+8) bf16 (80 B rows).
enum { MODE_DIR = 0, MODE_G16 = 1, MODE_CAT = 2 };
enum { EPI_F32 = 0, EPI_RELU = 1, EPI_MASK = 2, EPI_SPLIT_RELU = 3 };

#define ROWB     80                      // bytes per padded row
#define TILE_SZ  (128*ROWB)              // 10240
#define STAGE_SZ (4*TILE_SZ)             // 40960
#define SMEM_GEMM (2*STAGE_SZ)           // 81920

template<int MODE>
__device__ __forceinline__ const bf16* a_src(const bf16* A, const bf16* A2, const bf16* A3,
                                             int m, int K, int k0)
{
    if (MODE == MODE_CAT) {
        if (k0 < 512) return A  + (size_t)((m >> 4) * 64 + (m & 15)) * 512 + k0;
        if (k0 < 768) return A2 + (size_t)m * 256 + (k0 - 512);
        return A3 + (size_t)(m >> 4) * 64 + (k0 - 768);
    } else if (MODE == MODE_G16) {
        return A + (size_t)((m >> 4) * 64 + (m & 15)) * K + k0;
    } else {
        return A + (size_t)m * K + k0;
    }
}

template<int MODE, int EPI>
__global__ void __launch_bounds__(256, 1)
gemm_hmma(const bf16* __restrict__ Ah, const bf16* __restrict__ Al,
          const bf16* __restrict__ A2h, const bf16* __restrict__ A2l,
          const bf16* __restrict__ A3h, const bf16* __restrict__ A3l,
          const bf16* __restrict__ Bh, const bf16* __restrict__ Bl,   // [N,K]
          const float* __restrict__ bias,
          float* __restrict__ C, bf16* __restrict__ Ch, bf16* __restrict__ Cl,
          const unsigned char* __restrict__ smask,
          int K, int ldc)
{
    extern __shared__ char sm[];
    const uint32_t smb = smem_u32(sm);
    const int tid  = threadIdx.x;
    const int wid  = tid >> 5;
    const int lane = tid & 31;
    const int bm = blockIdx.y * 128;
    const int bn = blockIdx.x * 128;

    const int warp_m = wid & 3;          // 0..3 -> 32 rows each
    const int warp_n = wid >> 2;         // 0..1 -> 64 cols each

    float acc[2][8][4];
    #pragma unroll
    for (int mt = 0; mt < 2; mt++)
        #pragma unroll
        for (int nt = 0; nt < 8; nt++)
            #pragma unroll
            for (int r = 0; r < 4; r++) acc[mt][nt][r] = 0.0f;

    const int nch = K / 32;

    // ---- stage loader: 2048 16B chunks, 8 per thread ----
    auto load_stage = [&](int s, int k0) {
        const uint32_t stg = smb + s * STAGE_SZ;
        #pragma unroll
        for (int it = 0; it < 8; it++) {
            int idx = tid + it * 256;        // 0..2047
            int t4  = idx >> 9;              // tile 0..3
            int r   = (idx >> 2) & 127;      // row
            int c16 = idx & 3;               // 16B chunk in row
            uint32_t dst = stg + t4 * TILE_SZ + r * ROWB + c16 * 16;
            const bf16* src;
            if (t4 == 0)      src = a_src<MODE>(Ah, A2h, A3h, bm + r, K, k0) + c16 * 8;
            else if (t4 == 1) src = a_src<MODE>(Al, A2l, A3l, bm + r, K, k0) + c16 * 8;
            else if (t4 == 2) src = Bh + (size_t)(bn + r) * K + k0 + c16 * 8;
            else              src = Bl + (size_t)(bn + r) * K + k0 + c16 * 8;
            cp16(dst, src);
        }
    };

    load_stage(0, 0);
    CP_COMMIT();

    const int lrow = lane & 15;
    const int lcol = (lane >> 4) * 8;

    for (int c = 0; c < nch; c++) {
        if (c + 1 < nch) {
            load_stage((c + 1) & 1, (c + 1) * 32);
            CP_COMMIT();
            CP_WAIT(1);
        } else {
            CP_WAIT(0);
        }
        __syncthreads();

        const uint32_t stg = smb + (c & 1) * STAGE_SZ;
        #pragma unroll
        for (int ks = 0; ks < 2; ks++) {
            uint32_t ah[2][4], al[2][4], bh4[4][4], bl4[4][4];
            const uint32_t kb = (ks * 16 + lcol) * 2;
            #pragma unroll
            for (int mt = 0; mt < 2; mt++) {
                uint32_t ad = stg + (uint32_t)(warp_m * 32 + mt * 16 + lrow) * ROWB + kb;
                ldm_x4(ah[mt], ad);
                ldm_x4(al[mt], ad + TILE_SZ);
            }
            #pragma unroll
            for (int nq = 0; nq < 4; nq++) {
                uint32_t ad = stg + 2 * TILE_SZ
                            + (uint32_t)(warp_n * 64 + nq * 16 + lrow) * ROWB + kb;
                ldm_x4(bh4[nq], ad);
                ldm_x4(bl4[nq], ad + TILE_SZ);
            }
            #pragma unroll
            for (int mt = 0; mt < 2; mt++)
                #pragma unroll
                for (int nt = 0; nt < 8; nt++) {
                    const int nq = nt >> 1, j = nt & 1;
                    mma16816(acc[mt][nt], ah[mt], bh4[nq][j], bh4[nq][j + 2]);
                    mma16816(acc[mt][nt], ah[mt], bl4[nq][j], bl4[nq][j + 2]);
                    mma16816(acc[mt][nt], al[mt], bh4[nq][j], bh4[nq][j + 2]);
                }
        }
        __syncthreads();
    }

    // ---- epilogue ----
    #pragma unroll
    for (int mt = 0; mt < 2; mt++) {
        #pragma unroll
        for (int nt = 0; nt < 8; nt++) {
            const int row0 = bm + warp_m * 32 + mt * 16 + (lane >> 2);
            const int col  = bn + warp_n * 64 + nt * 8 + (lane & 3) * 2;
            const float b0 = bias[col], b1 = bias[col + 1];
            #pragma unroll
            for (int h = 0; h < 2; h++) {
                const int row = row0 + h * 8;
                float v0 = acc[mt][nt][h * 2 + 0] + b0;
                float v1 = acc[mt][nt][h * 2 + 1] + b1;
                if (EPI == EPI_RELU || EPI == EPI_SPLIT_RELU) {
                    v0 = fmaxf(v0, 0.0f); v1 = fmaxf(v1, 0.0f);
                }
                if (EPI == EPI_MASK) {
                    const int b = row >> 4, q = row & 15;
                    const float keep = smask[b * 64 + q] ? 0.0f : 1.0f;
                    v0 *= keep; v1 *= keep;
                }
                if (EPI == EPI_SPLIT_RELU) {
                    bf16 h0, l0, h1, l1;
                    split1(v0, h0, l0); split1(v1, h1, l1);
                    uint32_t pw = (uint32_t)__bfloat16_as_ushort(h0)
                                | ((uint32_t)__bfloat16_as_ushort(h1) << 16);
                    uint32_t plw = (uint32_t)__bfloat16_as_ushort(l0)
                                 | ((uint32_t)__bfloat16_as_ushort(l1) << 16);
                    *(uint32_t*)(Ch + (size_t)row * ldc + col) = pw;
                    *(uint32_t*)(Cl + (size_t)row * ldc + col) = plw;
                } else {
                    *(float2*)(C + (size_t)row * ldc + col) = make_float2(v0, v1);
                }
            }
        }
    }
}

// ---------------- reward projection ----------------
__global__ void rew_kernel(const float* __restrict__ prer,
                           const float* __restrict__ Wr,
                           const float* __restrict__ br,
                           bf16* __restrict__ outh, bf16* __restrict__ outl)
{
    int idx = blockIdx.x * blockDim.x + threadIdx.x;
    if (idx >= BSZ * RLD) return;
    int b = idx >> 6, j = idx & 63;
    float v = fmaxf(fmaf(prer[b], Wr[j], br[j]), 0.0f);
    bf16 h, l; split1(v, h, l);
    outh[idx] = h; outl[idx] = l;
}

// ---------------- attention: one block per (b, h) ----------------
__global__ void __launch_bounds__(128)
attn_kernel(const float* __restrict__ Qg, const float* __restrict__ Kg,
            const float* __restrict__ Vg, const unsigned char* __restrict__ obs,
            bf16* __restrict__ outh, bf16* __restrict__ outl)
{
    const int b = blockIdx.x >> 3;
    const int h = blockIdx.x & 7;
    const int tid = threadIdx.x;

    __shared__ float Qs[16][32];
    __shared__ float Ks[64][32];
    __shared__ float Vs[64][32];
    __shared__ float Ws[16][64];

    {
        int q = tid >> 3;
        int e4 = (tid & 7) * 4;
        *(float4*)&Qs[q][e4] =
            *(const float4*)(Qg + (size_t)(b * 16 + q) * 256 + h * 32 + e4);
    }
    #pragma unroll
    for (int i = 0; i < 4; i++) {
        int idx = tid + i * 128;
        int k = idx >> 3;
        int e4 = (idx & 7) * 4;
        *(float4*)&Ks[k][e4] =
            *(const float4*)(Kg + (size_t)(b * 64 + k) * 256 + h * 32 + e4);
        *(float4*)&Vs[k][e4] =
            *(const float4*)(Vg + (size_t)(b * 64 + k) * 256 + h * 32 + e4);
    }
    __syncthreads();

    const float scale = 0.17677669529663687f;
    #pragma unroll
    for (int i = 0; i < 8; i++) {
        int s = tid + i * 128;
        int q = s >> 6;
        int k = s & 63;
        bool masked = (k == q) || (obs[(size_t)b * 4096 + q * 64 + k] != 0);
        float d;
        if (!masked) {
            d = 0.0f;
            #pragma unroll
            for (int e = 0; e < 32; e++) d = fmaf(Qs[q][e], Ks[k][e], d);
            d *= scale;
        } else {
            d = -INFINITY;
        }
        Ws[q][k] = d;
    }
    __syncthreads();

    {
        int q = tid >> 3;
        int l = tid & 7;
        float vals[8];
        float mx = -INFINITY;
        #pragma unroll
        for (int i = 0; i < 8; i++) { vals[i] = Ws[q][l + i * 8]; mx = fmaxf(mx, vals[i]); }
        #pragma unroll
        for (int d2 = 4; d2 > 0; d2 >>= 1) mx = fmaxf(mx, __shfl_xor_sync(0xffffffffu, mx, d2, 8));
        if (mx == -INFINITY) {
            #pragma unroll
            for (int i = 0; i < 8; i++) vals[i] = 0.0f;
        } else {
            float sum = 0.0f;
            #pragma unroll
            for (int i = 0; i < 8; i++) { vals[i] = __expf(vals[i] - mx); sum += vals[i]; }
            #pragma unroll
            for (int d2 = 4; d2 > 0; d2 >>= 1) sum += __shfl_xor_sync(0xffffffffu, sum, d2, 8);
            float inv = 1.0f / sum;
            #pragma unroll
            for (int i = 0; i < 8; i++) vals[i] *= inv;
        }
        #pragma unroll
        for (int i = 0; i < 8; i++) Ws[q][l + i * 8] = vals[i];
    }
    __syncthreads();

    #pragma unroll
    for (int i = 0; i < 4; i++) {
        int o = tid + i * 128;
        int q = o >> 5;
        int e = o & 31;
        float acc = 0.0f;
        #pragma unroll
        for (int k = 0; k < 64; k++) acc = fmaf(Ws[q][k], Vs[k][e], acc);
        bf16 hh, ll; split1(acc, hh, ll);
        size_t oi = (size_t)(b * 16 + q) * 256 + h * 32 + e;
        outh[oi] = hh; outl[oi] = ll;
    }
}

// ---------------- GRU pointwise ----------------
__device__ __forceinline__ float sigmoidf_(float x) { return 1.0f / (1.0f + __expf(-x)); }

__global__ void gru_kernel(const float* __restrict__ gi, const float* __restrict__ gh,
                           const float* __restrict__ preh,
                           const unsigned char* __restrict__ smask,
                           float* __restrict__ hOut,
                           bf16* __restrict__ hOh, bf16* __restrict__ hOl)
{
    int t = blockIdx.x * blockDim.x + threadIdx.x;
    if (t >= M_AG * (HD / 4)) return;
    int m  = t >> 7;
    int j4 = (t & 127) * 4;
    size_t gb = (size_t)m * GID + j4;
    size_t hb = (size_t)m * HD + j4;

    float4 ir = *(const float4*)(gi + gb);
    float4 iz = *(const float4*)(gi + gb + 512);
    float4 in = *(const float4*)(gi + gb + 1024);
    float4 hr = *(const float4*)(gh + gb);
    float4 hz = *(const float4*)(gh + gb + 512);
    float4 hn = *(const float4*)(gh + gb + 1024);
    float4 hp = *(const float4*)(preh + hb);

    int b = m >> 4, q = m & 15;
    float keep = smask[b * 64 + q] ? 0.0f : 1.0f;

    float o[4];
    {
        float r = sigmoidf_(ir.x + hr.x), z = sigmoidf_(iz.x + hz.x);
        float n = tanhf(in.x + r * hn.x);
        o[0] = keep * ((1.0f - z) * n + z * hp.x);
    }
    {
        float r = sigmoidf_(ir.y + hr.y), z = sigmoidf_(iz.y + hz.y);
        float n = tanhf(in.y + r * hn.y);
        o[1] = keep * ((1.0f - z) * n + z * hp.y);
    }
    {
        float r = sigmoidf_(ir.z + hr.z), z = sigmoidf_(iz.z + hz.z);
        float n = tanhf(in.z + r * hn.z);
        o[2] = keep * ((1.0f - z) * n + z * hp.z);
    }
    {
        float r = sigmoidf_(ir.w + hr.w), z = sigmoidf_(iz.w + hz.w);
        float n = tanhf(in.w + r * hn.w);
        o[3] = keep * ((1.0f - z) * n + z * hp.w);
    }
    *(float4*)(hOut + hb) = make_float4(o[0], o[1], o[2], o[3]);

    bf16 h0,l0,h1,l1,h2,l2,h3,l3;
    split1(o[0],h0,l0); split1(o[1],h1,l1); split1(o[2],h2,l2); split1(o[3],h3,l3);
    uint32_t ph0 = (uint32_t)__bfloat16_as_ushort(h0) | ((uint32_t)__bfloat16_as_ushort(h1) << 16);
    uint32_t ph1 = (uint32_t)__bfloat16_as_ushort(h2) | ((uint32_t)__bfloat16_as_ushort(h3) << 16);
    uint32_t pl0 = (uint32_t)__bfloat16_as_ushort(l0) | ((uint32_t)__bfloat16_as_ushort(l1) << 16);
    uint32_t pl1 = (uint32_t)__bfloat16_as_ushort(l2) | ((uint32_t)__bfloat16_as_ushort(l3) << 16);
    *(uint2*)(hOh + hb) = make_uint2(ph0, ph1);
    *(uint2*)(hOl + hb) = make_uint2(pl0, pl1);
}

// ---------------- launch ----------------
extern "C" void kernel_launch(void* const* d_in, const int* in_sizes, int n_in,
                              void* d_out, int out_size)
{
    (void)in_sizes; (void)out_size;

    const float* state          = (const float*)d_in[0];
    const float* prer           = (const float*)d_in[1];
    const void*  obs_raw        = d_in[2];
    const void*  smask_raw      = d_in[3];
    const float* preh           = (const float*)d_in[4];

    const int base = (n_in >= 22) ? 6 : 5;
    const float* Wst  = (const float*)d_in[base + 0];   const float* bst  = (const float*)d_in[base + 1];
    const float* Wr   = (const float*)d_in[base + 2];   const float* br   = (const float*)d_in[base + 3];
    const float* Wq   = (const float*)d_in[base + 4];   const float* bq   = (const float*)d_in[base + 5];
    const float* Wk   = (const float*)d_in[base + 6];   const float* bk   = (const float*)d_in[base + 7];
    const float* Wv   = (const float*)d_in[base + 8];   const float* bv   = (const float*)d_in[base + 9];
    const float* Wih  = (const float*)d_in[base + 10];  const float* bih  = (const float*)d_in[base + 11];
    const float* Whh  = (const float*)d_in[base + 12];  const float* bhh  = (const float*)d_in[base + 13];
    const float* Wout = (const float*)d_in[base + 14];  const float* bout = (const float*)d_in[base + 15];

    float* params = (float*)d_out;
    float* hOut   = params + (size_t)M_AG * OUTD;

    float *Kb, *Vb, *Qb, *gib, *ghb;
    bf16 *sth, *stl, *emh, *eml, *phh, *phl, *ath, *atl, *rwh, *rwl, *hh, *hl;
    bf16 *wsth,*wstl,*wqh,*wql,*wkh,*wkl,*wvh,*wvl,*wihh,*wihl,*whhh,*whhl,*wouth,*woutl;
    unsigned char *obs, *smask;
    cudaGetSymbolAddress((void**)&Kb,  g_K);   cudaGetSymbolAddress((void**)&Vb,  g_V);
    cudaGetSymbolAddress((void**)&Qb,  g_Q);   cudaGetSymbolAddress((void**)&gib, g_gi);
    cudaGetSymbolAddress((void**)&ghb, g_gh);
    cudaGetSymbolAddress((void**)&sth, g_state_h); cudaGetSymbolAddress((void**)&stl, g_state_l);
    cudaGetSymbolAddress((void**)&emh, g_embed_h); cudaGetSymbolAddress((void**)&eml, g_embed_l);
    cudaGetSymbolAddress((void**)&phh, g_preh_h);  cudaGetSymbolAddress((void**)&phl, g_preh_l);
    cudaGetSymbolAddress((void**)&ath, g_att_h);   cudaGetSymbolAddress((void**)&atl, g_att_l);
    cudaGetSymbolAddress((void**)&rwh, g_rew_h);   cudaGetSymbolAddress((void**)&rwl, g_rew_l);
    cudaGetSymbolAddress((void**)&hh,  g_h_h);     cudaGetSymbolAddress((void**)&hl,  g_h_l);
    cudaGetSymbolAddress((void**)&wsth, g_WstT_h); cudaGetSymbolAddress((void**)&wstl, g_WstT_l);
    cudaGetSymbolAddress((void**)&wqh,  g_WqT_h);  cudaGetSymbolAddress((void**)&wql,  g_WqT_l);
    cudaGetSymbolAddress((void**)&wkh,  g_WkT_h);  cudaGetSymbolAddress((void**)&wkl,  g_WkT_l);
    cudaGetSymbolAddress((void**)&wvh,  g_WvT_h);  cudaGetSymbolAddress((void**)&wvl,  g_WvT_l);
    cudaGetSymbolAddress((void**)&wihh, g_WihT_h); cudaGetSymbolAddress((void**)&wihl, g_WihT_l);
    cudaGetSymbolAddress((void**)&whhh, g_WhhT_h); cudaGetSymbolAddress((void**)&whhl, g_WhhT_l);
    cudaGetSymbolAddress((void**)&wouth,g_WoutT_h);cudaGetSymbolAddress((void**)&woutl,g_WoutT_l);
    cudaGetSymbolAddress((void**)&obs,   g_obs_u8);
    cudaGetSymbolAddress((void**)&smask, g_sm_u8);

    cudaFuncSetAttribute(gemm_hmma<MODE_DIR, EPI_SPLIT_RELU>, cudaFuncAttributeMaxDynamicSharedMemorySize, SMEM_GEMM);
    cudaFuncSetAttribute(gemm_hmma<MODE_DIR, EPI_F32>,        cudaFuncAttributeMaxDynamicSharedMemorySize, SMEM_GEMM);
    cudaFuncSetAttribute(gemm_hmma<MODE_DIR, EPI_RELU>,       cudaFuncAttributeMaxDynamicSharedMemorySize, SMEM_GEMM);
    cudaFuncSetAttribute(gemm_hmma<MODE_G16, EPI_F32>,        cudaFuncAttributeMaxDynamicSharedMemorySize, SMEM_GEMM);
    cudaFuncSetAttribute(gemm_hmma<MODE_CAT, EPI_F32>,        cudaFuncAttributeMaxDynamicSharedMemorySize, SMEM_GEMM);
    cudaFuncSetAttribute(gemm_hmma<MODE_DIR, EPI_MASK>,       cudaFuncAttributeMaxDynamicSharedMemorySize, SMEM_GEMM);

    dim3 blk(256);

    // 0. conversions + masks
    conv_split_kernel<<<(M_FULL*DIN/4 + 255)/256, blk>>>(state, sth, stl, M_FULL*DIN/4);
    conv_split_kernel<<<(M_AG*HD/4 + 255)/256,    blk>>>(preh,  phh, phl, M_AG*HD/4);
    conv_splitT_kernel<<<(DIN*HD + 255)/256,  blk>>>(Wst,  wsth, wstl, DIN, HD);
    conv_splitT_kernel<<<(HD*AD + 255)/256,   blk>>>(Wq,   wqh,  wql,  HD,  AD);
    conv_splitT_kernel<<<(HD*AD + 255)/256,   blk>>>(Wk,   wkh,  wkl,  HD,  AD);
    conv_splitT_kernel<<<(HD*AD + 255)/256,   blk>>>(Wv,   wvh,  wvl,  HD,  AD);
    conv_splitT_kernel<<<(832*GID + 255)/256, blk>>>(Wih,  wihh, wihl, 832, GID);
    conv_splitT_kernel<<<(HD*GID + 255)/256,  blk>>>(Whh,  whhh, whhl, HD,  GID);
    conv_splitT_kernel<<<(HD*OUTD + 255)/256, blk>>>(Wout, wouth,woutl, HD, OUTD);

    detect_reset_kernel<<<1, 1>>>();
    detect_mask_kernel<<<256, 256>>>((const unsigned int*)obs_raw, (BSZ*NE*NE)/4);
    convert_mask_kernel<<<(BSZ*NE*NE + 255)/256, blk>>>(obs_raw, obs, BSZ*NE*NE);
    convert_mask_kernel<<<(BSZ*NE + 255)/256,    blk>>>(smask_raw, smask, BSZ*NE);

    // 1. embed = relu(state @ W_state + b): emits bf16 hi/lo directly
    gemm_hmma<MODE_DIR, EPI_SPLIT_RELU><<<dim3(HD/128, M_FULL/128), blk, SMEM_GEMM>>>(
        sth, stl, nullptr, nullptr, nullptr, nullptr, wsth, wstl,
        bst, nullptr, emh, eml, nullptr, DIN, HD);

    // 2. K = embed @ W_k + b
    gemm_hmma<MODE_DIR, EPI_F32><<<dim3(AD/128, M_FULL/128), blk, SMEM_GEMM>>>(
        emh, eml, nullptr, nullptr, nullptr, nullptr, wkh, wkl,
        bk, Kb, nullptr, nullptr, nullptr, HD, AD);

    // 3. V = relu(embed @ W_v + b)
    gemm_hmma<MODE_DIR, EPI_RELU><<<dim3(AD/128, M_FULL/128), blk, SMEM_GEMM>>>(
        emh, eml, nullptr, nullptr, nullptr, nullptr, wvh, wvl,
        bv, Vb, nullptr, nullptr, nullptr, HD, AD);

    // 4. Q = embed[:, :16 rows per batch] @ W_q + b
    gemm_hmma<MODE_G16, EPI_F32><<<dim3(AD/128, M_AG/128), blk, SMEM_GEMM>>>(
        emh, eml, nullptr, nullptr, nullptr, nullptr, wqh, wql,
        bq, Qb, nullptr, nullptr, nullptr, HD, AD);

    // 5. rew (hi/lo)
    rew_kernel<<<(BSZ*RLD + 255)/256, blk>>>(prer, Wr, br, rwh, rwl);

    // 6. attention
    attn_kernel<<<BSZ*NHD, 128>>>(Qb, Kb, Vb, obs, ath, atl);

    // 7. gi = concat(embed16, att, rew) @ W_ih + b, K=832
    gemm_hmma<MODE_CAT, EPI_F32><<<dim3(GID/128, M_AG/128), blk, SMEM_GEMM>>>(
        emh, eml, ath, atl, rwh, rwl, wihh, wihl,
        bih, gib, nullptr, nullptr, nullptr, HD + AD + RLD, GID);

    // 8. gh = pre_hidden @ W_hh + b
    gemm_hmma<MODE_DIR, EPI_F32><<<dim3(GID/128, M_AG/128), blk, SMEM_GEMM>>>(
        phh, phl, nullptr, nullptr, nullptr, nullptr, whhh, whhl,
        bhh, ghb, nullptr, nullptr, nullptr, HD, GID);

    // 9. GRU pointwise -> h (fp32 into d_out, plus hi/lo for GEMM10)
    gru_kernel<<<(M_AG*(HD/4) + 255)/256, blk>>>(gib, ghb, preh, smask, hOut, hh, hl);

    // 10. params = h @ W_out + b, masked
    gemm_hmma<MODE_DIR, EPI_MASK><<<dim3(OUTD/128, M_AG/128), blk, SMEM_GEMM>>>(
        hh, hl, nullptr, nullptr, nullptr, nullptr, wouth, woutl,
        bout, params, nullptr, nullptr, smask, HD, OUTD);
}

// round 7
// speedup vs baseline: 3.1074x; 1.0697x over previous
#include <cuda_runtime.h>
#include <cuda_bf16.h>
#include <math.h>
#include <stdint.h>

// ---------------- problem constants ----------------
#define BSZ     2048
#define NE      64
#define NA      16
#define DIN     128
#define HD      512
#define AD      256
#define NHD     8
#define ED      32
#define RLD     64
#define OUTD    128
#define M_FULL  (BSZ*NE)     // 131072
#define M_AG    (BSZ*NA)     // 32768
#define GID     1536         // 3*H

typedef __nv_bfloat16 bf16;

// ---------------- scratch (device globals; no allocs allowed) ----------------
__device__ __align__(256) float g_K  [(size_t)M_FULL*AD];
__device__ __align__(256) float g_V  [(size_t)M_FULL*AD];
__device__ __align__(256) float g_Q  [(size_t)M_AG*AD];
__device__ __align__(256) float g_gi [(size_t)M_AG*GID];
__device__ __align__(256) float g_gh [(size_t)M_AG*GID];
__device__ __align__(256) bf16 g_state_h[(size_t)M_FULL*DIN];
__device__ __align__(256) bf16 g_state_l[(size_t)M_FULL*DIN];
__device__ __align__(256) bf16 g_embed_h[(size_t)M_FULL*HD];
__device__ __align__(256) bf16 g_embed_l[(size_t)M_FULL*HD];
__device__ __align__(256) bf16 g_preh_h [(size_t)M_AG*HD];
__device__ __align__(256) bf16 g_preh_l [(size_t)M_AG*HD];
__device__ __align__(256) bf16 g_att_h  [(size_t)M_AG*AD];
__device__ __align__(256) bf16 g_att_l  [(size_t)M_AG*AD];
__device__ __align__(256) bf16 g_rew_h  [(size_t)BSZ*RLD];
__device__ __align__(256) bf16 g_rew_l  [(size_t)BSZ*RLD];
__device__ __align__(256) bf16 g_h_h    [(size_t)M_AG*HD];
__device__ __align__(256) bf16 g_h_l    [(size_t)M_AG*HD];
__device__ __align__(256) bf16 g_WstT_h[HD*DIN],  g_WstT_l[HD*DIN];
__device__ __align__(256) bf16 g_WqT_h [AD*HD],   g_WqT_l [AD*HD];
__device__ __align__(256) bf16 g_WkT_h [AD*HD],   g_WkT_l [AD*HD];
__device__ __align__(256) bf16 g_WvT_h [AD*HD],   g_WvT_l [AD*HD];
__device__ __align__(256) bf16 g_WihT_h[GID*832], g_WihT_l[GID*832];
__device__ __align__(256) bf16 g_WhhT_h[GID*HD],  g_WhhT_l[GID*HD];
__device__ __align__(256) bf16 g_WoutT_h[OUTD*HD],g_WoutT_l[OUTD*HD];
__device__ unsigned char g_obs_u8[(size_t)BSZ*NE*NE];
__device__ unsigned char g_sm_u8 [(size_t)BSZ*NE];
__device__ int g_mask_flags;

// ---------------- baseline-PTX helpers ----------------
__device__ __forceinline__ uint32_t smem_u32(const void* p) {
    uint32_t a;
    asm("{ .reg .u64 t; cvta.to.shared.u64 t, %1; cvt.u32.u64 %0, t; }" : "=r"(a) : "l"(p));
    return a;
}
__device__ __forceinline__ void cp16(uint32_t dst, const void* src) {
    asm volatile("cp.async.cg.shared.global [%0], [%1], 16;" :: "r"(dst), "l"(src));
}
#define CP_COMMIT()  asm volatile("cp.async.commit_group;")
#define CP_WAIT(n)   asm volatile("cp.async.wait_group %0;" :: "n"(n))

__device__ __forceinline__ void ldm_x4(uint32_t* r, uint32_t addr) {
    asm volatile("ldmatrix.sync.aligned.m8n8.x4.shared.b16 {%0,%1,%2,%3}, [%4];"
                 : "=r"(r[0]), "=r"(r[1]), "=r"(r[2]), "=r"(r[3]) : "r"(addr));
}
__device__ __forceinline__ void mma16816(float* c, const uint32_t* a,
                                         uint32_t b0, uint32_t b1) {
    asm volatile(
        "mma.sync.aligned.m16n8k16.row.col.f32.bf16.bf16.f32 "
        "{%0,%1,%2,%3},{%4,%5,%6,%7},{%8,%9},{%0,%1,%2,%3};"
        : "+f"(c[0]), "+f"(c[1]), "+f"(c[2]), "+f"(c[3])
        : "r"(a[0]), "r"(a[1]), "r"(a[2]), "r"(a[3]), "r"(b0), "r"(b1));
}

// ---------------- mask dtype detection ----------------
__global__ void detect_reset_kernel() { g_mask_flags = 0; }
__global__ void detect_mask_kernel(const unsigned int* __restrict__ w, int nwords)
{
    int local = 0;
    for (int i = blockIdx.x * blockDim.x + threadIdx.x; i < nwords;
         i += gridDim.x * blockDim.x) {
        unsigned int v = w[i];
        if (v == 0x3F800000u) local |= 2;
        else if (v > 1u) local |= 1;
    }
    for (int d = 16; d > 0; d >>= 1) local |= __shfl_xor_sync(0xffffffffu, local, d);
    if ((threadIdx.x & 31) == 0 && local) atomicOr(&g_mask_flags, local);
}
__global__ void convert_mask_kernel(const void* __restrict__ src,
                                    unsigned char* __restrict__ dst, int n)
{
    int i = blockIdx.x * blockDim.x + threadIdx.x;
    if (i >= n) return;
    int f = g_mask_flags;
    int mode = (f & 2) ? 2 : ((f & 1) ? 1 : 0);
    unsigned char v;
    if (mode == 1)      v = (((const unsigned char*)src)[i] != 0);
    else if (mode == 2) v = (((const unsigned int*)src)[i] != 0);
    else                v = (((const int*)src)[i] != 0);
    dst[i] = v;
}

// ---------------- fp32 -> bf16 hi/lo conversions ----------------
__device__ __forceinline__ void split1(float v, bf16& h, bf16& l) {
    h = __float2bfloat16_rn(v);
    l = __float2bfloat16_rn(v - __bfloat162float(h));
}
__global__ void conv_split_kernel(const float* __restrict__ src,
                                  bf16* __restrict__ h, bf16* __restrict__ l, int n4)
{
    int i = blockIdx.x * blockDim.x + threadIdx.x;
    if (i >= n4) return;
    float4 v = ((const float4*)src)[i];
    bf16 h0,l0,h1,l1,h2,l2,h3,l3;
    split1(v.x,h0,l0); split1(v.y,h1,l1); split1(v.z,h2,l2); split1(v.w,h3,l3);
    uint32_t ph0 = (uint32_t)__bfloat16_as_ushort(h0) | ((uint32_t)__bfloat16_as_ushort(h1) << 16);
    uint32_t ph1 = (uint32_t)__bfloat16_as_ushort(h2) | ((uint32_t)__bfloat16_as_ushort(h3) << 16);
    uint32_t pl0 = (uint32_t)__bfloat16_as_ushort(l0) | ((uint32_t)__bfloat16_as_ushort(l1) << 16);
    uint32_t pl1 = (uint32_t)__bfloat16_as_ushort(l2) | ((uint32_t)__bfloat16_as_ushort(l3) << 16);
    ((uint2*)h)[i] = make_uint2(ph0, ph1);
    ((uint2*)l)[i] = make_uint2(pl0, pl1);
}
__global__ void conv_splitT_kernel(const float* __restrict__ src,
                                   bf16* __restrict__ h, bf16* __restrict__ l,
                                   int K, int N)
{
    int i = blockIdx.x * blockDim.x + threadIdx.x;
    if (i >= K * N) return;
    int k = i / N, n = i % N;
    bf16 hh, ll;
    split1(src[i], hh, ll);
    h[(size_t)n * K + k] = hh;
    l[(size_t)n * K + k] = ll;
}

// ---------------- HMMA bf16-split GEMM ----------------
// C[M,N] = act(A@B^T + bias), B as [N,K]. CTA tile 128 x BN, BK=32,
// 3-stage cp.async pipeline, one __syncthreads per chunk.
enum { MODE_DIR = 0, MODE_G16 = 1, MODE_CAT = 2 };
enum { EPI_F32 = 0, EPI_RELU = 1, EPI_MASK = 2, EPI_SPLIT_RELU = 3 };

#define ROWB 80      // bytes per padded 32-bf16 row

template<int BN> struct GP {
    static const int STAGE_ROWS = 256 + 2 * BN;          // Ah,Al,Bh,Bl
    static const int STAGE_SZ   = STAGE_ROWS * ROWB;
    static const int SMEM       = 3 * STAGE_SZ;
    static const int WARPS_M    = (BN == 256) ? 2 : 4;
    static const int MT         = 8 / WARPS_M;           // m16 tiles per warp
};

template<int MODE>
__device__ __forceinline__ const bf16* a_src(const bf16* A, const bf16* A2, const bf16* A3,
                                             int m, int K, int k0)
{
    if (MODE == MODE_CAT) {
        if (k0 < 512) return A  + (size_t)((m >> 4) * 64 + (m & 15)) * 512 + k0;
        if (k0 < 768) return A2 + (size_t)m * 256 + (k0 - 512);
        return A3 + (size_t)(m >> 4) * 64 + (k0 - 768);
    } else if (MODE == MODE_G16) {
        return A + (size_t)((m >> 4) * 64 + (m & 15)) * K + k0;
    } else {
        return A + (size_t)m * K + k0;
    }
}

template<int BN, int MODE, int EPI>
__global__ void __launch_bounds__(256, 1)
gemm_hmma(const bf16* __restrict__ Ah, const bf16* __restrict__ Al,
          const bf16* __restrict__ A2h, const bf16* __restrict__ A2l,
          const bf16* __restrict__ A3h, const bf16* __restrict__ A3l,
          const bf16* __restrict__ Bh, const bf16* __restrict__ Bl,   // [N,K]
          const float* __restrict__ bias,
          float* __restrict__ C, bf16* __restrict__ Ch, bf16* __restrict__ Cl,
          const unsigned char* __restrict__ smask,
          int K, int ldc)
{
    extern __shared__ char sm[];
    const uint32_t smb = smem_u32(sm);
    const int tid  = threadIdx.x;
    const int wid  = tid >> 5;
    const int lane = tid & 31;
    const int bm = blockIdx.y * 128;
    const int bn = blockIdx.x * BN;

    const int warp_m = wid % GP<BN>::WARPS_M;
    const int warp_n = wid / GP<BN>::WARPS_M;
    const int MT = GP<BN>::MT;

    float acc[GP<BN>::MT][8][4];
    #pragma unroll
    for (int mt = 0; mt < GP<BN>::MT; mt++)
        #pragma unroll
        for (int nt = 0; nt < 8; nt++)
            #pragma unroll
            for (int r = 0; r < 4; r++) acc[mt][nt][r] = 0.0f;

    const int nch = K / 32;

    // stage loader: (256+2BN)*4 16B chunks
    auto load_stage = [&](int s, int k0) {
        const uint32_t stg = smb + s * GP<BN>::STAGE_SZ;
        const int iters = GP<BN>::STAGE_ROWS * 4 / 256;
        #pragma unroll
        for (int it = 0; it < iters; it++) {
            int idx  = tid + it * 256;
            int grow = idx >> 2;
            int c16  = idx & 3;
            uint32_t dst = stg + grow * ROWB + c16 * 16;
            const bf16* src;
            if (grow < 128)            src = a_src<MODE>(Ah, A2h, A3h, bm + grow, K, k0) + c16 * 8;
            else if (grow < 256)       src = a_src<MODE>(Al, A2l, A3l, bm + grow - 128, K, k0) + c16 * 8;
            else if (grow < 256 + BN)  src = Bh + (size_t)(bn + grow - 256) * K + k0 + c16 * 8;
            else                       src = Bl + (size_t)(bn + grow - 256 - BN) * K + k0 + c16 * 8;
            cp16(dst, src);
        }
    };

    load_stage(0, 0);
    CP_COMMIT();
    if (nch > 1) { load_stage(1, 32); CP_COMMIT(); }

    const int lrow = lane & 15;
    const uint32_t koff = ((lane >> 4) * 8) * 2;

    for (int c = 0; c < nch; c++) {
        if (c + 1 < nch) { CP_WAIT(1); } else { CP_WAIT(0); }
        __syncthreads();

        const uint32_t stg = smb + (c % 3) * GP<BN>::STAGE_SZ;
        #pragma unroll
        for (int ks = 0; ks < 2; ks++) {
            const uint32_t kb = ks * 32 + koff;
            uint32_t ah[GP<BN>::MT][4], al[GP<BN>::MT][4];
            #pragma unroll
            for (int mt = 0; mt < GP<BN>::MT; mt++) {
                const uint32_t arow = warp_m * (MT * 16) + mt * 16 + lrow;
                ldm_x4(ah[mt], stg + arow * ROWB + kb);
                ldm_x4(al[mt], stg + (128 + arow) * ROWB + kb);
            }
            #pragma unroll
            for (int nq = 0; nq < 4; nq++) {
                const uint32_t brow = warp_n * 64 + nq * 16 + lrow;
                uint32_t bh4[4], bl4[4];
                ldm_x4(bh4, stg + (256 + brow) * ROWB + kb);
                ldm_x4(bl4, stg + (256 + BN + brow) * ROWB + kb);
                #pragma unroll
                for (int mt = 0; mt < GP<BN>::MT; mt++)
                    #pragma unroll
                    for (int j = 0; j < 2; j++) {
                        const int nt = nq * 2 + j;
                        mma16816(acc[mt][nt], ah[mt], bh4[j], bh4[j + 2]);
                        mma16816(acc[mt][nt], ah[mt], bl4[j], bl4[j + 2]);
                        mma16816(acc[mt][nt], al[mt], bh4[j], bh4[j + 2]);
                    }
            }
        }

        if (c + 2 < nch) {
            load_stage((c + 2) % 3, (c + 2) * 32);
            CP_COMMIT();
        }
    }

    // ---- epilogue ----
    #pragma unroll
    for (int mt = 0; mt < GP<BN>::MT; mt++) {
        #pragma unroll
        for (int nt = 0; nt < 8; nt++) {
            const int row0 = bm + warp_m * (MT * 16) + mt * 16 + (lane >> 2);
            const int col  = bn + warp_n * 64 + nt * 8 + (lane & 3) * 2;
            const float b0 = bias[col], b1 = bias[col + 1];
            #pragma unroll
            for (int h = 0; h < 2; h++) {
                const int row = row0 + h * 8;
                float v0 = acc[mt][nt][h * 2 + 0] + b0;
                float v1 = acc[mt][nt][h * 2 + 1] + b1;
                if (EPI == EPI_RELU || EPI == EPI_SPLIT_RELU) {
                    v0 = fmaxf(v0, 0.0f); v1 = fmaxf(v1, 0.0f);
                }
                if (EPI == EPI_MASK) {
                    const int b = row >> 4, q = row & 15;
                    const float keep = smask[b * 64 + q] ? 0.0f : 1.0f;
                    v0 *= keep; v1 *= keep;
                }
                if (EPI == EPI_SPLIT_RELU) {
                    bf16 h0, l0, h1, l1;
                    split1(v0, h0, l0); split1(v1, h1, l1);
                    uint32_t pw = (uint32_t)__bfloat16_as_ushort(h0)
                                | ((uint32_t)__bfloat16_as_ushort(h1) << 16);
                    uint32_t plw = (uint32_t)__bfloat16_as_ushort(l0)
                                 | ((uint32_t)__bfloat16_as_ushort(l1) << 16);
                    *(uint32_t*)(Ch + (size_t)row * ldc + col) = pw;
                    *(uint32_t*)(Cl + (size_t)row * ldc + col) = plw;
                } else {
                    *(float2*)(C + (size_t)row * ldc + col) = make_float2(v0, v1);
                }
            }
        }
    }
}

// ---------------- reward projection ----------------
__global__ void rew_kernel(const float* __restrict__ prer,
                           const float* __restrict__ Wr,
                           const float* __restrict__ br,
                           bf16* __restrict__ outh, bf16* __restrict__ outl)
{
    int idx = blockIdx.x * blockDim.x + threadIdx.x;
    if (idx >= BSZ * RLD) return;
    int b = idx >> 6, j = idx & 63;
    float v = fmaxf(fmaf(prer[b], Wr[j], br[j]), 0.0f);
    bf16 h, l; split1(v, h, l);
    outh[idx] = h; outl[idx] = l;
}

// ---------------- attention: one block per (b, h) ----------------
__global__ void __launch_bounds__(128)
attn_kernel(const float* __restrict__ Qg, const float* __restrict__ Kg,
            const float* __restrict__ Vg, const unsigned char* __restrict__ obs,
            bf16* __restrict__ outh, bf16* __restrict__ outl)
{
    const int b = blockIdx.x >> 3;
    const int h = blockIdx.x & 7;
    const int tid = threadIdx.x;

    __shared__ float Qs[16][32];
    __shared__ float Ks[64][32];
    __shared__ float Vs[64][32];
    __shared__ float Ws[16][64];

    {
        int q = tid >> 3;
        int e4 = (tid & 7) * 4;
        *(float4*)&Qs[q][e4] =
            *(const float4*)(Qg + (size_t)(b * 16 + q) * 256 + h * 32 + e4);
    }
    #pragma unroll
    for (int i = 0; i < 4; i++) {
        int idx = tid + i * 128;
        int k = idx >> 3;
        int e4 = (idx & 7) * 4;
        *(float4*)&Ks[k][e4] =
            *(const float4*)(Kg + (size_t)(b * 64 + k) * 256 + h * 32 + e4);
        *(float4*)&Vs[k][e4] =
            *(const float4*)(Vg + (size_t)(b * 64 + k) * 256 + h * 32 + e4);
    }
    __syncthreads();

    const float scale = 0.17677669529663687f;
    #pragma unroll
    for (int i = 0; i < 8; i++) {
        int s = tid + i * 128;
        int q = s >> 6;
        int k = s & 63;
        bool masked = (k == q) || (obs[(size_t)b * 4096 + q * 64 + k] != 0);
        float d;
        if (!masked) {
            d = 0.0f;
            #pragma unroll
            for (int e = 0; e < 32; e++) d = fmaf(Qs[q][e], Ks[k][e], d);
            d *= scale;
        } else {
            d = -INFINITY;
        }
        Ws[q][k] = d;
    }
    __syncthreads();

    {
        int q = tid >> 3;
        int l = tid & 7;
        float vals[8];
        float mx = -INFINITY;
        #pragma unroll
        for (int i = 0; i < 8; i++) { vals[i] = Ws[q][l + i * 8]; mx = fmaxf(mx, vals[i]); }
        #pragma unroll
        for (int d2 = 4; d2 > 0; d2 >>= 1) mx = fmaxf(mx, __shfl_xor_sync(0xffffffffu, mx, d2, 8));
        if (mx == -INFINITY) {
            #pragma unroll
            for (int i = 0; i < 8; i++) vals[i] = 0.0f;
        } else {
            float sum = 0.0f;
            #pragma unroll
            for (int i = 0; i < 8; i++) { vals[i] = __expf(vals[i] - mx); sum += vals[i]; }
            #pragma unroll
            for (int d2 = 4; d2 > 0; d2 >>= 1) sum += __shfl_xor_sync(0xffffffffu, sum, d2, 8);
            float inv = 1.0f / sum;
            #pragma unroll
            for (int i = 0; i < 8; i++) vals[i] *= inv;
        }
        #pragma unroll
        for (int i = 0; i < 8; i++) Ws[q][l + i * 8] = vals[i];
    }
    __syncthreads();

    #pragma unroll
    for (int i = 0; i < 4; i++) {
        int o = tid + i * 128;
        int q = o >> 5;
        int e = o & 31;
        float acc = 0.0f;
        #pragma unroll
        for (int k = 0; k < 64; k++) acc = fmaf(Ws[q][k], Vs[k][e], acc);
        bf16 hh, ll; split1(acc, hh, ll);
        size_t oi = (size_t)(b * 16 + q) * 256 + h * 32 + e;
        outh[oi] = hh; outl[oi] = ll;
    }
}

// ---------------- GRU pointwise ----------------
__device__ __forceinline__ float sigmoidf_(float x) { return 1.0f / (1.0f + __expf(-x)); }

__global__ void gru_kernel(const float* __restrict__ gi, const float* __restrict__ gh,
                           const float* __restrict__ preh,
                           const unsigned char* __restrict__ smask,
                           float* __restrict__ hOut,
                           bf16* __restrict__ hOh, bf16* __restrict__ hOl)
{
    int t = blockIdx.x * blockDim.x + threadIdx.x;
    if (t >= M_AG * (HD / 4)) return;
    int m  = t >> 7;
    int j4 = (t & 127) * 4;
    size_t gb = (size_t)m * GID + j4;
    size_t hb = (size_t)m * HD + j4;

    float4 ir = *(const float4*)(gi + gb);
    float4 iz = *(const float4*)(gi + gb + 512);
    float4 in = *(const float4*)(gi + gb + 1024);
    float4 hr = *(const float4*)(gh + gb);
    float4 hz = *(const float4*)(gh + gb + 512);
    float4 hn = *(const float4*)(gh + gb + 1024);
    float4 hp = *(const float4*)(preh + hb);

    int b = m >> 4, q = m & 15;
    float keep = smask[b * 64 + q] ? 0.0f : 1.0f;

    float o[4];
    {
        float r = sigmoidf_(ir.x + hr.x), z = sigmoidf_(iz.x + hz.x);
        float n = tanhf(in.x + r * hn.x);
        o[0] = keep * ((1.0f - z) * n + z * hp.x);
    }
    {
        float r = sigmoidf_(ir.y + hr.y), z = sigmoidf_(iz.y + hz.y);
        float n = tanhf(in.y + r * hn.y);
        o[1] = keep * ((1.0f - z) * n + z * hp.y);
    }
    {
        float r = sigmoidf_(ir.z + hr.z), z = sigmoidf_(iz.z + hz.z);
        float n = tanhf(in.z + r * hn.z);
        o[2] = keep * ((1.0f - z) * n + z * hp.z);
    }
    {
        float r = sigmoidf_(ir.w + hr.w), z = sigmoidf_(iz.w + hz.w);
        float n = tanhf(in.w + r * hn.w);
        o[3] = keep * ((1.0f - z) * n + z * hp.w);
    }
    *(float4*)(hOut + hb) = make_float4(o[0], o[1], o[2], o[3]);

    bf16 h0,l0,h1,l1,h2,l2,h3,l3;
    split1(o[0],h0,l0); split1(o[1],h1,l1); split1(o[2],h2,l2); split1(o[3],h3,l3);
    uint32_t ph0 = (uint32_t)__bfloat16_as_ushort(h0) | ((uint32_t)__bfloat16_as_ushort(h1) << 16);
    uint32_t ph1 = (uint32_t)__bfloat16_as_ushort(h2) | ((uint32_t)__bfloat16_as_ushort(h3) << 16);
    uint32_t pl0 = (uint32_t)__bfloat16_as_ushort(l0) | ((uint32_t)__bfloat16_as_ushort(l1) << 16);
    uint32_t pl1 = (uint32_t)__bfloat16_as_ushort(l2) | ((uint32_t)__bfloat16_as_ushort(l3) << 16);
    *(uint2*)(hOh + hb) = make_uint2(ph0, ph1);
    *(uint2*)(hOl + hb) = make_uint2(pl0, pl1);
}

// ---------------- launch ----------------
extern "C" void kernel_launch(void* const* d_in, const int* in_sizes, int n_in,
                              void* d_out, int out_size)
{
    (void)in_sizes; (void)out_size;

    const float* state          = (const float*)d_in[0];
    const float* prer           = (const float*)d_in[1];
    const void*  obs_raw        = d_in[2];
    const void*  smask_raw      = d_in[3];
    const float* preh           = (const float*)d_in[4];

    const int base = (n_in >= 22) ? 6 : 5;
    const float* Wst  = (const float*)d_in[base + 0];   const float* bst  = (const float*)d_in[base + 1];
    const float* Wr   = (const float*)d_in[base + 2];   const float* br   = (const float*)d_in[base + 3];
    const float* Wq   = (const float*)d_in[base + 4];   const float* bq   = (const float*)d_in[base + 5];
    const float* Wk   = (const float*)d_in[base + 6];   const float* bk   = (const float*)d_in[base + 7];
    const float* Wv   = (const float*)d_in[base + 8];   const float* bv   = (const float*)d_in[base + 9];
    const float* Wih  = (const float*)d_in[base + 10];  const float* bih  = (const float*)d_in[base + 11];
    const float* Whh  = (const float*)d_in[base + 12];  const float* bhh  = (const float*)d_in[base + 13];
    const float* Wout = (const float*)d_in[base + 14];  const float* bout = (const float*)d_in[base + 15];

    float* params = (float*)d_out;
    float* hOut   = params + (size_t)M_AG * OUTD;

    float *Kb, *Vb, *Qb, *gib, *ghb;
    bf16 *sth, *stl, *emh, *eml, *phh, *phl, *ath, *atl, *rwh, *rwl, *hh, *hl;
    bf16 *wsth,*wstl,*wqh,*wql,*wkh,*wkl,*wvh,*wvl,*wihh,*wihl,*whhh,*whhl,*wouth,*woutl;
    unsigned char *obs, *smask;
    cudaGetSymbolAddress((void**)&Kb,  g_K);   cudaGetSymbolAddress((void**)&Vb,  g_V);
    cudaGetSymbolAddress((void**)&Qb,  g_Q);   cudaGetSymbolAddress((void**)&gib, g_gi);
    cudaGetSymbolAddress((void**)&ghb, g_gh);
    cudaGetSymbolAddress((void**)&sth, g_state_h); cudaGetSymbolAddress((void**)&stl, g_state_l);
    cudaGetSymbolAddress((void**)&emh, g_embed_h); cudaGetSymbolAddress((void**)&eml, g_embed_l);
    cudaGetSymbolAddress((void**)&phh, g_preh_h);  cudaGetSymbolAddress((void**)&phl, g_preh_l);
    cudaGetSymbolAddress((void**)&ath, g_att_h);   cudaGetSymbolAddress((void**)&atl, g_att_l);
    cudaGetSymbolAddress((void**)&rwh, g_rew_h);   cudaGetSymbolAddress((void**)&rwl, g_rew_l);
    cudaGetSymbolAddress((void**)&hh,  g_h_h);     cudaGetSymbolAddress((void**)&hl,  g_h_l);
    cudaGetSymbolAddress((void**)&wsth, g_WstT_h); cudaGetSymbolAddress((void**)&wstl, g_WstT_l);
    cudaGetSymbolAddress((void**)&wqh,  g_WqT_h);  cudaGetSymbolAddress((void**)&wql,  g_WqT_l);
    cudaGetSymbolAddress((void**)&wkh,  g_WkT_h);  cudaGetSymbolAddress((void**)&wkl,  g_WkT_l);
    cudaGetSymbolAddress((void**)&wvh,  g_WvT_h);  cudaGetSymbolAddress((void**)&wvl,  g_WvT_l);
    cudaGetSymbolAddress((void**)&wihh, g_WihT_h); cudaGetSymbolAddress((void**)&wihl, g_WihT_l);
    cudaGetSymbolAddress((void**)&whhh, g_WhhT_h); cudaGetSymbolAddress((void**)&whhl, g_WhhT_l);
    cudaGetSymbolAddress((void**)&wouth,g_WoutT_h);cudaGetSymbolAddress((void**)&woutl,g_WoutT_l);
    cudaGetSymbolAddress((void**)&obs,   g_obs_u8);
    cudaGetSymbolAddress((void**)&smask, g_sm_u8);

    const int SM256 = GP<256>::SMEM;   // 184320
    const int SM128 = GP<128>::SMEM;   // 122880
    cudaFuncSetAttribute(gemm_hmma<256, MODE_DIR, EPI_SPLIT_RELU>, cudaFuncAttributeMaxDynamicSharedMemorySize, SM256);
    cudaFuncSetAttribute(gemm_hmma<256, MODE_DIR, EPI_F32>,        cudaFuncAttributeMaxDynamicSharedMemorySize, SM256);
    cudaFuncSetAttribute(gemm_hmma<256, MODE_DIR, EPI_RELU>,       cudaFuncAttributeMaxDynamicSharedMemorySize, SM256);
    cudaFuncSetAttribute(gemm_hmma<256, MODE_G16, EPI_F32>,        cudaFuncAttributeMaxDynamicSharedMemorySize, SM256);
    cudaFuncSetAttribute(gemm_hmma<256, MODE_CAT, EPI_F32>,        cudaFuncAttributeMaxDynamicSharedMemorySize, SM256);
    cudaFuncSetAttribute(gemm_hmma<128, MODE_DIR, EPI_MASK>,       cudaFuncAttributeMaxDynamicSharedMemorySize, SM128);

    dim3 blk(256);

    // 0. conversions + masks
    conv_split_kernel<<<(M_FULL*DIN/4 + 255)/256, blk>>>(state, sth, stl, M_FULL*DIN/4);
    conv_split_kernel<<<(M_AG*HD/4 + 255)/256,    blk>>>(preh,  phh, phl, M_AG*HD/4);
    conv_splitT_kernel<<<(DIN*HD + 255)/256,  blk>>>(Wst,  wsth, wstl, DIN, HD);
    conv_splitT_kernel<<<(HD*AD + 255)/256,   blk>>>(Wq,   wqh,  wql,  HD,  AD);
    conv_splitT_kernel<<<(HD*AD + 255)/256,   blk>>>(Wk,   wkh,  wkl,  HD,  AD);
    conv_splitT_kernel<<<(HD*AD + 255)/256,   blk>>>(Wv,   wvh,  wvl,  HD,  AD);
    conv_splitT_kernel<<<(832*GID + 255)/256, blk>>>(Wih,  wihh, wihl, 832, GID);
    conv_splitT_kernel<<<(HD*GID + 255)/256,  blk>>>(Whh,  whhh, whhl, HD,  GID);
    conv_splitT_kernel<<<(HD*OUTD + 255)/256, blk>>>(Wout, wouth,woutl, HD, OUTD);

    detect_reset_kernel<<<1, 1>>>();
    detect_mask_kernel<<<256, 256>>>((const unsigned int*)obs_raw, (BSZ*NE*NE)/4);
    convert_mask_kernel<<<(BSZ*NE*NE + 255)/256, blk>>>(obs_raw, obs, BSZ*NE*NE);
    convert_mask_kernel<<<(BSZ*NE + 255)/256,    blk>>>(smask_raw, smask, BSZ*NE);

    // 1. embed = relu(state @ W_state + b): emits bf16 hi/lo directly
    gemm_hmma<256, MODE_DIR, EPI_SPLIT_RELU><<<dim3(HD/256, M_FULL/128), blk, SM256>>>(
        sth, stl, nullptr, nullptr, nullptr, nullptr, wsth, wstl,
        bst, nullptr, emh, eml, nullptr, DIN, HD);

    // 2. K = embed @ W_k + b
    gemm_hmma<256, MODE_DIR, EPI_F32><<<dim3(AD/256, M_FULL/128), blk, SM256>>>(
        emh, eml, nullptr, nullptr, nullptr, nullptr, wkh, wkl,
        bk, Kb, nullptr, nullptr, nullptr, HD, AD);

    // 3. V = relu(embed @ W_v + b)
    gemm_hmma<256, MODE_DIR, EPI_RELU><<<dim3(AD/256, M_FULL/128), blk, SM256>>>(
        emh, eml, nullptr, nullptr, nullptr, nullptr, wvh, wvl,
        bv, Vb, nullptr, nullptr, nullptr, HD, AD);

    // 4. Q = embed[:, :16 rows per batch] @ W_q + b
    gemm_hmma<256, MODE_G16, EPI_F32><<<dim3(AD/256, M_AG/128), blk, SM256>>>(
        emh, eml, nullptr, nullptr, nullptr, nullptr, wqh, wql,
        bq, Qb, nullptr, nullptr, nullptr, HD, AD);

    // 5. rew (hi/lo)
    rew_kernel<<<(BSZ*RLD + 255)/256, blk>>>(prer, Wr, br, rwh, rwl);

    // 6. attention
    attn_kernel<<<BSZ*NHD, 128>>>(Qb, Kb, Vb, obs, ath, atl);

    // 7. gi = concat(embed16, att, rew) @ W_ih + b, K=832
    gemm_hmma<256, MODE_CAT, EPI_F32><<<dim3(GID/256, M_AG/128), blk, SM256>>>(
        emh, eml, ath, atl, rwh, rwl, wihh, wihl,
        bih, gib, nullptr, nullptr, nullptr, HD + AD + RLD, GID);

    // 8. gh = pre_hidden @ W_hh + b
    gemm_hmma<256, MODE_DIR, EPI_F32><<<dim3(GID/256, M_AG/128), blk, SM256>>>(
        phh, phl, nullptr, nullptr, nullptr, nullptr, whhh, whhl,
        bhh, ghb, nullptr, nullptr, nullptr, HD, GID);

    // 9. GRU pointwise -> h (fp32 into d_out, plus hi/lo for GEMM10)
    gru_kernel<<<(M_AG*(HD/4) + 255)/256, blk>>>(gib, ghb, preh, smask, hOut, hh, hl);

    // 10. params = h @ W_out + b, masked
    gemm_hmma<128, MODE_DIR, EPI_MASK><<<dim3(OUTD/128, M_AG/128), blk, SM128>>>(
        hh, hl, nullptr, nullptr, nullptr, nullptr, wouth, woutl,
        bout, params, nullptr, nullptr, smask, HD, OUTD);
}

// round 8
// speedup vs baseline: 5.6580x; 1.8208x over previous
#include <cuda_runtime.h>
#include <cuda_bf16.h>
#include <math.h>
#include <stdint.h>

// ---------------- problem constants ----------------
#define BSZ     2048
#define NE      64
#define NA      16
#define DIN     128
#define HD      512
#define AD      256
#define NHD     8
#define ED      32
#define RLD     64
#define OUTD    128
#define M_FULL  (BSZ*NE)     // 131072
#define M_AG    (BSZ*NA)     // 32768
#define GID     1536         // 3*H

// ---------------- scratch (device globals; no allocs allowed) ----------------
__device__ __align__(256) float g_K  [(size_t)M_FULL*AD];
__device__ __align__(256) float g_V  [(size_t)M_FULL*AD];
__device__ __align__(256) float g_Q  [(size_t)M_AG*AD];
__device__ __align__(256) float g_gi [(size_t)M_AG*GID];
__device__ __align__(256) float g_gh [(size_t)M_AG*GID];
// tf32-rounded fp32 activations
__device__ __align__(256) float g_state_t[(size_t)M_FULL*DIN];
__device__ __align__(256) float g_embed_t[(size_t)M_FULL*HD];
__device__ __align__(256) float g_preh_t [(size_t)M_AG*HD];
__device__ __align__(256) float g_att_t  [(size_t)M_AG*AD];
__device__ __align__(256) float g_rew_t  [(size_t)BSZ*RLD];
__device__ __align__(256) float g_h_t    [(size_t)M_AG*HD];
// tf32-rounded transposed weights [N, K]
__device__ __align__(256) float g_WstT [HD*DIN];
__device__ __align__(256) float g_WqT  [AD*HD];
__device__ __align__(256) float g_WkT  [AD*HD];
__device__ __align__(256) float g_WvT  [AD*HD];
__device__ __align__(256) float g_WihT [GID*832];
__device__ __align__(256) float g_WhhT [GID*HD];
__device__ __align__(256) float g_WoutT[OUTD*HD];
__device__ unsigned char g_obs_u8[(size_t)BSZ*NE*NE];
__device__ unsigned char g_sm_u8 [(size_t)BSZ*NE];
__device__ int g_mask_flags;

// ---------------- baseline-PTX helpers ----------------
__device__ __forceinline__ uint32_t smem_u32(const void* p) {
    uint32_t a;
    asm("{ .reg .u64 t; cvta.to.shared.u64 t, %1; cvt.u32.u64 %0, t; }" : "=r"(a) : "l"(p));
    return a;
}
__device__ __forceinline__ void cp16(uint32_t dst, const void* src) {
    asm volatile("cp.async.cg.shared.global [%0], [%1], 16;" :: "r"(dst), "l"(src));
}
#define CP_COMMIT()  asm volatile("cp.async.commit_group;")
#define CP_WAIT(n)   asm volatile("cp.async.wait_group %0;" :: "n"(n))

__device__ __forceinline__ void ldm_x4(uint32_t* r, uint32_t addr) {
    asm volatile("ldmatrix.sync.aligned.m8n8.x4.shared.b16 {%0,%1,%2,%3}, [%4];"
                 : "=r"(r[0]), "=r"(r[1]), "=r"(r[2]), "=r"(r[3]) : "r"(addr));
}
__device__ __forceinline__ void mma_tf32(float* c, const uint32_t* a,
                                         uint32_t b0, uint32_t b1) {
    asm volatile(
        "mma.sync.aligned.m16n8k8.row.col.f32.tf32.tf32.f32 "
        "{%0,%1,%2,%3},{%4,%5,%6,%7},{%8,%9},{%0,%1,%2,%3};"
        : "+f"(c[0]), "+f"(c[1]), "+f"(c[2]), "+f"(c[3])
        : "r"(a[0]), "r"(a[1]), "r"(a[2]), "r"(a[3]), "r"(b0), "r"(b1));
}
__device__ __forceinline__ float rna_tf32(float v) {
    uint32_t r;
    asm("cvt.rna.tf32.f32 %0, %1;" : "=r"(r) : "f"(v));
    return __uint_as_float(r);
}

// ---------------- mask dtype detection ----------------
__global__ void detect_reset_kernel() { g_mask_flags = 0; }
__global__ void detect_mask_kernel(const unsigned int* __restrict__ w, int nwords)
{
    int local = 0;
    for (int i = blockIdx.x * blockDim.x + threadIdx.x; i < nwords;
         i += gridDim.x * blockDim.x) {
        unsigned int v = w[i];
        if (v == 0x3F800000u) local |= 2;
        else if (v > 1u) local |= 1;
    }
    for (int d = 16; d > 0; d >>= 1) local |= __shfl_xor_sync(0xffffffffu, local, d);
    if ((threadIdx.x & 31) == 0 && local) atomicOr(&g_mask_flags, local);
}
__global__ void convert_mask_kernel(const void* __restrict__ src,
                                    unsigned char* __restrict__ dst, int n)
{
    int i = blockIdx.x * blockDim.x + threadIdx.x;
    if (i >= n) return;
    int f = g_mask_flags;
    int mode = (f & 2) ? 2 : ((f & 1) ? 1 : 0);
    unsigned char v;
    if (mode == 1)      v = (((const unsigned char*)src)[i] != 0);
    else if (mode == 2) v = (((const unsigned int*)src)[i] != 0);
    else                v = (((const int*)src)[i] != 0);
    dst[i] = v;
}

// ---------------- tf32 rounding conversions ----------------
__global__ void conv_rnd_kernel(const float* __restrict__ src,
                                float* __restrict__ dst, int n4)
{
    int i = blockIdx.x * blockDim.x + threadIdx.x;
    if (i >= n4) return;
    float4 v = ((const float4*)src)[i];
    v.x = rna_tf32(v.x); v.y = rna_tf32(v.y);
    v.z = rna_tf32(v.z); v.w = rna_tf32(v.w);
    ((float4*)dst)[i] = v;
}
// transpose-round: src [K, N] fp32 -> dst [N, K] tf32-rounded fp32
__global__ void conv_rndT_kernel(const float* __restrict__ src,
                                 float* __restrict__ dst, int K, int N)
{
    int i = blockIdx.x * blockDim.x + threadIdx.x;
    if (i >= K * N) return;
    int k = i / N, n = i % N;
    dst[(size_t)n * K + k] = rna_tf32(src[i]);
}

// ---------------- tf32 HMMA GEMM ----------------
// C[M,N] = act(A@B^T + bias), B as [N,K] tf32-rounded. CTA tile 128 x BN,
// BK=32, 3-stage cp.async pipeline, XOR chunk swizzle, ldmatrix fragments.
enum { MODE_DIR = 0, MODE_G16 = 1, MODE_CAT = 2 };
enum { EPI_F32 = 0, EPI_RELU = 1, EPI_MASK = 2, EPI_RELU_RND = 3 };

template<int BN> struct GP {
    static const int STAGE_ROWS = 128 + BN;      // A rows then B rows
    static const int STAGE_SZ   = STAGE_ROWS * 128;   // 128 B per row (32 fp32)
    static const int SMEM       = 3 * STAGE_SZ;
    static const int WARPS_M    = (BN == 256) ? 2 : 4;
    static const int MT         = 8 / WARPS_M;   // 16-row tiles per warp
};

template<int MODE>
__device__ __forceinline__ const float* a_src(const float* A, const float* A2, const float* A3,
                                              int m, int K, int k0)
{
    if (MODE == MODE_CAT) {
        if (k0 < 512) return A  + (size_t)((m >> 4) * 64 + (m & 15)) * 512 + k0;
        if (k0 < 768) return A2 + (size_t)m * 256 + (k0 - 512);
        return A3 + (size_t)(m >> 4) * 64 + (k0 - 768);
    } else if (MODE == MODE_G16) {
        return A + (size_t)((m >> 4) * 64 + (m & 15)) * K + k0;
    } else {
        return A + (size_t)m * K + k0;
    }
}

template<int BN, int MODE, int EPI>
__global__ void __launch_bounds__(256, 1)
gemm_tf32(const float* __restrict__ A, const float* __restrict__ A2,
          const float* __restrict__ A3, const float* __restrict__ B,  // [N,K]
          const float* __restrict__ bias, float* __restrict__ C,
          const unsigned char* __restrict__ smask,
          int K, int ldc)
{
    extern __shared__ char sm[];
    const uint32_t smb = smem_u32(sm);
    const int tid  = threadIdx.x;
    const int wid  = tid >> 5;
    const int lane = tid & 31;
    const int bm = blockIdx.y * 128;
    const int bn = blockIdx.x * BN;

    const int warp_m = wid % GP<BN>::WARPS_M;
    const int warp_n = wid / GP<BN>::WARPS_M;
    const int MT = GP<BN>::MT;

    float acc[GP<BN>::MT][8][4];
    #pragma unroll
    for (int mt = 0; mt < GP<BN>::MT; mt++)
        #pragma unroll
        for (int nt = 0; nt < 8; nt++)
            #pragma unroll
            for (int r = 0; r < 4; r++) acc[mt][nt][r] = 0.0f;

    const int nch = K / 32;

    // stage loader: STAGE_ROWS*8 16B chunks; XOR swizzle on chunk index
    auto load_stage = [&](int s, int k0) {
        const uint32_t stg = smb + s * GP<BN>::STAGE_SZ;
        const int iters = GP<BN>::STAGE_ROWS * 8 / 256;
        #pragma unroll
        for (int it = 0; it < iters; it++) {
            int idx  = tid + it * 256;
            int grow = idx >> 3;
            int c16  = idx & 7;
            uint32_t dst = stg + grow * 128 + (uint32_t)((c16 ^ (grow & 7)) * 16);
            const float* src;
            if (grow < 128) src = a_src<MODE>(A, A2, A3, bm + grow, K, k0) + c16 * 4;
            else            src = B + (size_t)(bn + grow - 128) * K + k0 + c16 * 4;
            cp16(dst, src);
        }
    };

    load_stage(0, 0);
    CP_COMMIT();
    if (nch > 1) { load_stage(1, 32); CP_COMMIT(); }

    const int T = lane >> 3;      // ldmatrix tile index for this lane's address
    const int tr = lane & 7;      // row within tile

    for (int c = 0; c < nch; c++) {
        if (c + 1 < nch) { CP_WAIT(1); } else { CP_WAIT(0); }
        __syncthreads();

        const uint32_t stg = smb + (c % 3) * GP<BN>::STAGE_SZ;
        #pragma unroll
        for (int s = 0; s < 4; s++) {          // k8 slices in chunk (chunks 2s, 2s+1)
            uint32_t a[GP<BN>::MT][4];
            #pragma unroll
            for (int mt = 0; mt < GP<BN>::MT; mt++) {
                // tiles: T0 rows0-7 chk2s, T1 rows8-15 chk2s, T2 rows0-7 chk2s+1, T3 rows8-15 chk2s+1
                uint32_t row = warp_m * (MT * 16) + mt * 16 + (T & 1) * 8 + tr;
                uint32_t chk = 2 * s + (T >> 1);
                ldm_x4(a[mt], stg + row * 128 + ((chk ^ (row & 7)) * 16));
            }
            #pragma unroll
            for (int nq = 0; nq < 4; nq++) {   // pairs of 8-col tiles
                // tiles: T0 n0-7 chk2s (b0,nt0), T1 n0-7 chk2s+1 (b1,nt0), T2/T3 nt1
                uint32_t nrow = 128 + warp_n * 64 + nq * 16 + (T >> 1) * 8 + tr;
                uint32_t chk = 2 * s + (T & 1);
                uint32_t b[4];
                ldm_x4(b, stg + nrow * 128 + ((chk ^ (nrow & 7)) * 16));
                #pragma unroll
                for (int mt = 0; mt < GP<BN>::MT; mt++) {
                    mma_tf32(acc[mt][nq * 2 + 0], a[mt], b[0], b[1]);
                    mma_tf32(acc[mt][nq * 2 + 1], a[mt], b[2], b[3]);
                }
            }
        }

        if (c + 2 < nch) {
            load_stage((c + 2) % 3, (c + 2) * 32);
            CP_COMMIT();
        }
    }

    // ---- epilogue ----
    #pragma unroll
    for (int mt = 0; mt < GP<BN>::MT; mt++) {
        #pragma unroll
        for (int nt = 0; nt < 8; nt++) {
            const int row0 = bm + warp_m * (MT * 16) + mt * 16 + (lane >> 2);
            const int col  = bn + warp_n * 64 + nt * 8 + (lane & 3) * 2;
            const float b0 = bias[col], b1 = bias[col + 1];
            #pragma unroll
            for (int h = 0; h < 2; h++) {
                const int row = row0 + h * 8;
                float v0 = acc[mt][nt][h * 2 + 0] + b0;
                float v1 = acc[mt][nt][h * 2 + 1] + b1;
                if (EPI == EPI_RELU || EPI == EPI_RELU_RND) {
                    v0 = fmaxf(v0, 0.0f); v1 = fmaxf(v1, 0.0f);
                }
                if (EPI == EPI_MASK) {
                    const int b = row >> 4, q = row & 15;
                    const float keep = smask[b * 64 + q] ? 0.0f : 1.0f;
                    v0 *= keep; v1 *= keep;
                }
                if (EPI == EPI_RELU_RND) { v0 = rna_tf32(v0); v1 = rna_tf32(v1); }
                *(float2*)(C + (size_t)row * ldc + col) = make_float2(v0, v1);
            }
        }
    }
}

// ---------------- reward projection (tf32-rounded out) ----------------
__global__ void rew_kernel(const float* __restrict__ prer,
                           const float* __restrict__ Wr,
                           const float* __restrict__ br,
                           float* __restrict__ out)
{
    int idx = blockIdx.x * blockDim.x + threadIdx.x;
    if (idx >= BSZ * RLD) return;
    int b = idx >> 6, j = idx & 63;
    out[idx] = rna_tf32(fmaxf(fmaf(prer[b], Wr[j], br[j]), 0.0f));
}

// ---------------- attention: one block per (b, h); conflict-free Ks ----------
__global__ void __launch_bounds__(128)
attn_kernel(const float* __restrict__ Qg, const float* __restrict__ Kg,
            const float* __restrict__ Vg, const unsigned char* __restrict__ obs,
            float* __restrict__ outT)
{
    const int b = blockIdx.x >> 3;
    const int h = blockIdx.x & 7;
    const int tid = threadIdx.x;

    __shared__ float Qs[16][32];
    __shared__ float Ks[64][33];   // padded: score-loop bank = (k+e)%32, conflict-free
    __shared__ float Vs[64][32];
    __shared__ float Ws[16][68];   // padded for softmax lane access

    {
        int q = tid >> 3;
        int e4 = (tid & 7) * 4;
        *(float4*)&Qs[q][e4] =
            *(const float4*)(Qg + (size_t)(b * 16 + q) * 256 + h * 32 + e4);
    }
    #pragma unroll
    for (int i = 0; i < 4; i++) {
        int idx = tid + i * 128;
        int k = idx >> 3;
        int e4 = (idx & 7) * 4;
        float4 kv = *(const float4*)(Kg + (size_t)(b * 64 + k) * 256 + h * 32 + e4);
        Ks[k][e4 + 0] = kv.x; Ks[k][e4 + 1] = kv.y;
        Ks[k][e4 + 2] = kv.z; Ks[k][e4 + 3] = kv.w;
        *(float4*)&Vs[k][e4] =
            *(const float4*)(Vg + (size_t)(b * 64 + k) * 256 + h * 32 + e4);
    }
    __syncthreads();

    const float scale = 0.17677669529663687f;
    #pragma unroll
    for (int i = 0; i < 8; i++) {
        int s = tid + i * 128;
        int q = s >> 6;
        int k = s & 63;
        bool masked = (k == q) || (obs[(size_t)b * 4096 + q * 64 + k] != 0);
        float d;
        if (!masked) {
            d = 0.0f;
            #pragma unroll
            for (int e = 0; e < 32; e++) d = fmaf(Qs[q][e], Ks[k][e], d);
            d *= scale;
        } else {
            d = -INFINITY;
        }
        Ws[q][k] = d;
    }
    __syncthreads();

    {
        int q = tid >> 3;
        int l = tid & 7;
        float vals[8];
        float mx = -INFINITY;
        #pragma unroll
        for (int i = 0; i < 8; i++) { vals[i] = Ws[q][l + i * 8]; mx = fmaxf(mx, vals[i]); }
        #pragma unroll
        for (int d2 = 4; d2 > 0; d2 >>= 1) mx = fmaxf(mx, __shfl_xor_sync(0xffffffffu, mx, d2, 8));
        if (mx == -INFINITY) {
            #pragma unroll
            for (int i = 0; i < 8; i++) vals[i] = 0.0f;
        } else {
            float sum = 0.0f;
            #pragma unroll
            for (int i = 0; i < 8; i++) { vals[i] = __expf(vals[i] - mx); sum += vals[i]; }
            #pragma unroll
            for (int d2 = 4; d2 > 0; d2 >>= 1) sum += __shfl_xor_sync(0xffffffffu, sum, d2, 8);
            float inv = 1.0f / sum;
            #pragma unroll
            for (int i = 0; i < 8; i++) vals[i] *= inv;
        }
        #pragma unroll
        for (int i = 0; i < 8; i++) Ws[q][l + i * 8] = vals[i];
    }
    __syncthreads();

    #pragma unroll
    for (int i = 0; i < 4; i++) {
        int o = tid + i * 128;
        int q = o >> 5;
        int e = o & 31;
        float acc = 0.0f;
        #pragma unroll
        for (int k = 0; k < 64; k++) acc = fmaf(Ws[q][k], Vs[k][e], acc);
        outT[(size_t)(b * 16 + q) * 256 + h * 32 + e] = rna_tf32(acc);
    }
}

// ---------------- GRU pointwise ----------------
__device__ __forceinline__ float sigmoidf_(float x) { return 1.0f / (1.0f + __expf(-x)); }

__global__ void gru_kernel(const float* __restrict__ gi, const float* __restrict__ gh,
                           const float* __restrict__ preh,
                           const unsigned char* __restrict__ smask,
                           float* __restrict__ hOut, float* __restrict__ hT)
{
    int t = blockIdx.x * blockDim.x + threadIdx.x;
    if (t >= M_AG * (HD / 4)) return;
    int m  = t >> 7;
    int j4 = (t & 127) * 4;
    size_t gb = (size_t)m * GID + j4;
    size_t hb = (size_t)m * HD + j4;

    float4 ir = *(const float4*)(gi + gb);
    float4 iz = *(const float4*)(gi + gb + 512);
    float4 in = *(const float4*)(gi + gb + 1024);
    float4 hr = *(const float4*)(gh + gb);
    float4 hz = *(const float4*)(gh + gb + 512);
    float4 hn = *(const float4*)(gh + gb + 1024);
    float4 hp = *(const float4*)(preh + hb);

    int b = m >> 4, q = m & 15;
    float keep = smask[b * 64 + q] ? 0.0f : 1.0f;

    float o[4];
    {
        float r = sigmoidf_(ir.x + hr.x), z = sigmoidf_(iz.x + hz.x);
        float n = tanhf(in.x + r * hn.x);
        o[0] = keep * ((1.0f - z) * n + z * hp.x);
    }
    {
        float r = sigmoidf_(ir.y + hr.y), z = sigmoidf_(iz.y + hz.y);
        float n = tanhf(in.y + r * hn.y);
        o[1] = keep * ((1.0f - z) * n + z * hp.y);
    }
    {
        float r = sigmoidf_(ir.z + hr.z), z = sigmoidf_(iz.z + hz.z);
        float n = tanhf(in.z + r * hn.z);
        o[2] = keep * ((1.0f - z) * n + z * hp.z);
    }
    {
        float r = sigmoidf_(ir.w + hr.w), z = sigmoidf_(iz.w + hz.w);
        float n = tanhf(in.w + r * hn.w);
        o[3] = keep * ((1.0f - z) * n + z * hp.w);
    }
    *(float4*)(hOut + hb) = make_float4(o[0], o[1], o[2], o[3]);
    *(float4*)(hT + hb) = make_float4(rna_tf32(o[0]), rna_tf32(o[1]),
                                      rna_tf32(o[2]), rna_tf32(o[3]));
}

// ---------------- launch ----------------
extern "C" void kernel_launch(void* const* d_in, const int* in_sizes, int n_in,
                              void* d_out, int out_size)
{
    (void)in_sizes; (void)out_size;

    const float* state          = (const float*)d_in[0];
    const float* prer           = (const float*)d_in[1];
    const void*  obs_raw        = d_in[2];
    const void*  smask_raw      = d_in[3];
    const float* preh           = (const float*)d_in[4];

    const int base = (n_in >= 22) ? 6 : 5;
    const float* Wst  = (const float*)d_in[base + 0];   const float* bst  = (const float*)d_in[base + 1];
    const float* Wr   = (const float*)d_in[base + 2];   const float* br   = (const float*)d_in[base + 3];
    const float* Wq   = (const float*)d_in[base + 4];   const float* bq   = (const float*)d_in[base + 5];
    const float* Wk   = (const float*)d_in[base + 6];   const float* bk   = (const float*)d_in[base + 7];
    const float* Wv   = (const float*)d_in[base + 8];   const float* bv   = (const float*)d_in[base + 9];
    const float* Wih  = (const float*)d_in[base + 10];  const float* bih  = (const float*)d_in[base + 11];
    const float* Whh  = (const float*)d_in[base + 12];  const float* bhh  = (const float*)d_in[base + 13];
    const float* Wout = (const float*)d_in[base + 14];  const float* bout = (const float*)d_in[base + 15];

    float* params = (float*)d_out;
    float* hOut   = params + (size_t)M_AG * OUTD;

    float *Kb, *Vb, *Qb, *gib, *ghb;
    float *stt, *emt, *pht, *att, *rwt, *ht;
    float *wstT, *wqT, *wkT, *wvT, *wihT, *whhT, *woutT;
    unsigned char *obs, *smask;
    cudaGetSymbolAddress((void**)&Kb,  g_K);   cudaGetSymbolAddress((void**)&Vb,  g_V);
    cudaGetSymbolAddress((void**)&Qb,  g_Q);   cudaGetSymbolAddress((void**)&gib, g_gi);
    cudaGetSymbolAddress((void**)&ghb, g_gh);
    cudaGetSymbolAddress((void**)&stt, g_state_t);
    cudaGetSymbolAddress((void**)&emt, g_embed_t);
    cudaGetSymbolAddress((void**)&pht, g_preh_t);
    cudaGetSymbolAddress((void**)&att, g_att_t);
    cudaGetSymbolAddress((void**)&rwt, g_rew_t);
    cudaGetSymbolAddress((void**)&ht,  g_h_t);
    cudaGetSymbolAddress((void**)&wstT,  g_WstT);
    cudaGetSymbolAddress((void**)&wqT,   g_WqT);
    cudaGetSymbolAddress((void**)&wkT,   g_WkT);
    cudaGetSymbolAddress((void**)&wvT,   g_WvT);
    cudaGetSymbolAddress((void**)&wihT,  g_WihT);
    cudaGetSymbolAddress((void**)&whhT,  g_WhhT);
    cudaGetSymbolAddress((void**)&woutT, g_WoutT);
    cudaGetSymbolAddress((void**)&obs,   g_obs_u8);
    cudaGetSymbolAddress((void**)&smask, g_sm_u8);

    const int SM256 = GP<256>::SMEM;   // 147456
    const int SM128 = GP<128>::SMEM;   // 98304
    cudaFuncSetAttribute(gemm_tf32<256, MODE_DIR, EPI_RELU_RND>, cudaFuncAttributeMaxDynamicSharedMemorySize, SM256);
    cudaFuncSetAttribute(gemm_tf32<256, MODE_DIR, EPI_F32>,      cudaFuncAttributeMaxDynamicSharedMemorySize, SM256);
    cudaFuncSetAttribute(gemm_tf32<256, MODE_DIR, EPI_RELU>,     cudaFuncAttributeMaxDynamicSharedMemorySize, SM256);
    cudaFuncSetAttribute(gemm_tf32<256, MODE_G16, EPI_F32>,      cudaFuncAttributeMaxDynamicSharedMemorySize, SM256);
    cudaFuncSetAttribute(gemm_tf32<256, MODE_CAT, EPI_F32>,      cudaFuncAttributeMaxDynamicSharedMemorySize, SM256);
    cudaFuncSetAttribute(gemm_tf32<128, MODE_DIR, EPI_MASK>,     cudaFuncAttributeMaxDynamicSharedMemorySize, SM128);

    dim3 blk(256);

    // 0. tf32 rounding + masks
    conv_rnd_kernel<<<(M_FULL*DIN/4 + 255)/256, blk>>>(state, stt, M_FULL*DIN/4);
    conv_rnd_kernel<<<(M_AG*HD/4 + 255)/256,    blk>>>(preh,  pht, M_AG*HD/4);
    conv_rndT_kernel<<<(DIN*HD + 255)/256,  blk>>>(Wst,  wstT,  DIN, HD);
    conv_rndT_kernel<<<(HD*AD + 255)/256,   blk>>>(Wq,   wqT,   HD,  AD);
    conv_rndT_kernel<<<(HD*AD + 255)/256,   blk>>>(Wk,   wkT,   HD,  AD);
    conv_rndT_kernel<<<(HD*AD + 255)/256,   blk>>>(Wv,   wvT,   HD,  AD);
    conv_rndT_kernel<<<(832*GID + 255)/256, blk>>>(Wih,  wihT,  832, GID);
    conv_rndT_kernel<<<(HD*GID + 255)/256,  blk>>>(Whh,  whhT,  HD,  GID);
    conv_rndT_kernel<<<(HD*OUTD + 255)/256, blk>>>(Wout, woutT, HD,  OUTD);

    detect_reset_kernel<<<1, 1>>>();
    detect_mask_kernel<<<256, 256>>>((const unsigned int*)obs_raw, (BSZ*NE*NE)/4);
    convert_mask_kernel<<<(BSZ*NE*NE + 255)/256, blk>>>(obs_raw, obs, BSZ*NE*NE);
    convert_mask_kernel<<<(BSZ*NE + 255)/256,    blk>>>(smask_raw, smask, BSZ*NE);

    // 1. embed = relu(state @ W_state + b), tf32-rounded output
    gemm_tf32<256, MODE_DIR, EPI_RELU_RND><<<dim3(HD/256, M_FULL/128), blk, SM256>>>(
        stt, nullptr, nullptr, wstT, bst, emt, nullptr, DIN, HD);

    // 2. K = embed @ W_k + b
    gemm_tf32<256, MODE_DIR, EPI_F32><<<dim3(AD/256, M_FULL/128), blk, SM256>>>(
        emt, nullptr, nullptr, wkT, bk, Kb, nullptr, HD, AD);

    // 3. V = relu(embed @ W_v + b)
    gemm_tf32<256, MODE_DIR, EPI_RELU><<<dim3(AD/256, M_FULL/128), blk, SM256>>>(
        emt, nullptr, nullptr, wvT, bv, Vb, nullptr, HD, AD);

    // 4. Q = embed[:, :16 rows per batch] @ W_q + b
    gemm_tf32<256, MODE_G16, EPI_F32><<<dim3(AD/256, M_AG/128), blk, SM256>>>(
        emt, nullptr, nullptr, wqT, bq, Qb, nullptr, HD, AD);

    // 5. rew
    rew_kernel<<<(BSZ*RLD + 255)/256, blk>>>(prer, Wr, br, rwt);

    // 6. attention
    attn_kernel<<<BSZ*NHD, 128>>>(Qb, Kb, Vb, obs, att);

    // 7. gi = concat(embed16, att, rew) @ W_ih + b, K=832
    gemm_tf32<256, MODE_CAT, EPI_F32><<<dim3(GID/256, M_AG/128), blk, SM256>>>(
        emt, att, rwt, wihT, bih, gib, nullptr, HD + AD + RLD, GID);

    // 8. gh = pre_hidden @ W_hh + b
    gemm_tf32<256, MODE_DIR, EPI_F32><<<dim3(GID/256, M_AG/128), blk, SM256>>>(
        pht, nullptr, nullptr, whhT, bhh, ghb, nullptr, HD, GID);

    // 9. GRU pointwise -> h (fp32 into d_out, tf32-rounded copy for GEMM10)
    gru_kernel<<<(M_AG*(HD/4) + 255)/256, blk>>>(gib, ghb, preh, smask, hOut, ht);

    // 10. params = h @ W_out + b, masked
    gemm_tf32<128, MODE_DIR, EPI_MASK><<<dim3(OUTD/128, M_AG/128), blk, SM128>>>(
        ht, nullptr, nullptr, woutT, bout, params, smask, HD, OUTD);
}